// round 1
// baseline (speedup 1.0000x reference)
#include <cuda_runtime.h>

#define BATCH 4
#define SEQ   2048
#define EMB   1024
#define HEADS 16
#define HDIM  64
#define MTOT  (BATCH*SEQ)      // 8192
#define QKVN  (3*EMB)          // 3072

// Scratch (static device memory — no allocations allowed)
__device__ float g_q[BATCH*HEADS*SEQ*HDIM];   // 32 MB
__device__ float g_k[BATCH*HEADS*SEQ*HDIM];   // 32 MB
__device__ float g_v[BATCH*HEADS*SEQ*HDIM];   // 32 MB
__device__ float g_att[MTOT*EMB];             // 32 MB

// ---------------------------------------------------------------------------
// Tiled NT SGEMM: C[M,N] = A[M,K] @ B[N,K]^T + bias
// BM=BN=128, BK=16, 256 threads, 8x8 micro-tile per thread.
// MODE 0: A = x, B = w_qkv, epilogue scatters into g_q/g_k/g_v ([b,h,n,d])
// MODE 1: A = g_att, B = w_proj, epilogue writes Cout (d_out) with bias
// ---------------------------------------------------------------------------
template<int MODE>
__global__ __launch_bounds__(256)
void sgemm_nt(const float* __restrict__ A, const float* __restrict__ Bm,
              const float* __restrict__ bias, float* __restrict__ Cout, int K)
{
    __shared__ float As[16][132];   // [k][m], padded: float4-aligned (132*4=528)
    __shared__ float Bs[16][132];   // [k][n]

    const int tid = threadIdx.x;
    const int tx  = tid & 15;       // 0..15 (N dir)
    const int ty  = tid >> 4;       // 0..15 (M dir)
    const int m0  = blockIdx.y * 128;
    const int n0  = blockIdx.x * 128;

    const float* Aptr = (MODE == 1) ? (const float*)g_att : A;
    const float* Ag = Aptr + (size_t)m0 * K;
    const float* Bg = Bm   + (size_t)n0 * K;

    float acc[8][8];
#pragma unroll
    for (int i = 0; i < 8; ++i)
#pragma unroll
        for (int j = 0; j < 8; ++j) acc[i][j] = 0.f;

    for (int k0 = 0; k0 < K; k0 += 16) {
        // load 128x16 tiles of A and B (transposed into [k][mn])
#pragma unroll
        for (int l = 0; l < 2; ++l) {
            int idx = tid + l * 256;          // 0..511 (float4 index)
            int row = idx >> 2;               // 0..127
            int c4  = (idx & 3) << 2;         // 0,4,8,12
            float4 va = *(const float4*)(Ag + (size_t)row * K + k0 + c4);
            As[c4+0][row] = va.x; As[c4+1][row] = va.y;
            As[c4+2][row] = va.z; As[c4+3][row] = va.w;
            float4 vb = *(const float4*)(Bg + (size_t)row * K + k0 + c4);
            Bs[c4+0][row] = vb.x; Bs[c4+1][row] = vb.y;
            Bs[c4+2][row] = vb.z; Bs[c4+3][row] = vb.w;
        }
        __syncthreads();

#pragma unroll
        for (int kk = 0; kk < 16; ++kk) {
            float a[8], b[8];
            *(float4*)&a[0] = *(const float4*)&As[kk][ty*8];
            *(float4*)&a[4] = *(const float4*)&As[kk][ty*8 + 4];
            *(float4*)&b[0] = *(const float4*)&Bs[kk][tx*8];
            *(float4*)&b[4] = *(const float4*)&Bs[kk][tx*8 + 4];
#pragma unroll
            for (int i = 0; i < 8; ++i)
#pragma unroll
                for (int j = 0; j < 8; ++j)
                    acc[i][j] += a[i] * b[j];
        }
        __syncthreads();
    }

    // bias for this thread's 8 output columns
    float bv[8];
    *(float4*)&bv[0] = *(const float4*)(bias + n0 + tx*8);
    *(float4*)&bv[4] = *(const float4*)(bias + n0 + tx*8 + 4);

    if (MODE == 1) {
        // plain store: Cout[m, n0+tx*8 .. +7], row stride EMB
#pragma unroll
        for (int i = 0; i < 8; ++i) {
            int m = m0 + ty*8 + i;
            float* p = Cout + (size_t)m * EMB + n0 + tx*8;
            float4 r0 = make_float4(acc[i][0]+bv[0], acc[i][1]+bv[1],
                                    acc[i][2]+bv[2], acc[i][3]+bv[3]);
            float4 r1 = make_float4(acc[i][4]+bv[4], acc[i][5]+bv[5],
                                    acc[i][6]+bv[6], acc[i][7]+bv[7]);
            *(float4*)p       = r0;
            *(float4*)(p + 4) = r1;
        }
    } else {
        // scatter into q/k/v: col = which*1024 + h*64 + d
        const int which = n0 >> 10;                 // uniform per block
        float* dst = (which == 0) ? g_q : ((which == 1) ? g_k : g_v);
        const int e  = (n0 + tx*8) & 1023;
        const int h  = e >> 6;
        const int d0 = e & 63;                      // multiple of 8 -> no h crossing
#pragma unroll
        for (int i = 0; i < 8; ++i) {
            int m  = m0 + ty*8 + i;
            int b_ = m >> 11;
            int n_ = m & 2047;
            float* p = dst + (((size_t)(b_*HEADS + h) * SEQ + n_) * HDIM) + d0;
            float4 r0 = make_float4(acc[i][0]+bv[0], acc[i][1]+bv[1],
                                    acc[i][2]+bv[2], acc[i][3]+bv[3]);
            float4 r1 = make_float4(acc[i][4]+bv[4], acc[i][5]+bv[5],
                                    acc[i][6]+bv[6], acc[i][7]+bv[7]);
            *(float4*)p       = r0;
            *(float4*)(p + 4) = r1;
        }
    }
}

// ---------------------------------------------------------------------------
// Flash attention: one query row per thread (q,o in regs), 32-key SMEM tiles,
// online softmax with per-tile max. Output written in [b, n, emb] layout.
// grid = (SEQ/128, BATCH*HEADS), block = 128
// ---------------------------------------------------------------------------
__global__ __launch_bounds__(128)
void flash_attn()
{
    const int bh = blockIdx.y;                      // 0..63  (b*16 + h)
    const int qi = blockIdx.x * 128 + threadIdx.x;  // query index within (b,h)

    const float* Qp = g_q + ((size_t)bh * SEQ + qi) * HDIM;
    const float* Kb = g_k + (size_t)bh * SEQ * HDIM;
    const float* Vb = g_v + (size_t)bh * SEQ * HDIM;

    float q[64], o[64];
#pragma unroll
    for (int t = 0; t < 16; ++t) {
        float4 v = *(const float4*)(Qp + 4*t);
        q[4*t+0] = v.x; q[4*t+1] = v.y; q[4*t+2] = v.z; q[4*t+3] = v.w;
    }
#pragma unroll
    for (int t = 0; t < 64; ++t) o[t] = 0.f;

    float mrun = -1e30f, lrun = 0.f;
    const float scale = 0.125f;     // 1/sqrt(64)

    __shared__ float Ks[32][64];    // 8 KB
    __shared__ float Vs[32][64];    // 8 KB

    for (int k0 = 0; k0 < SEQ; k0 += 32) {
        __syncthreads();
        // load 32x64 K and V tiles (128 threads x 4 float4 each)
#pragma unroll
        for (int l = 0; l < 4; ++l) {
            int idx = threadIdx.x + l * 128;   // 0..511 (float4 idx)
            int r = idx >> 4;                  // 0..31
            int c = (idx & 15) << 2;           // 0..60
            *(float4*)&Ks[r][c] = *(const float4*)(Kb + (size_t)(k0 + r) * HDIM + c);
            *(float4*)&Vs[r][c] = *(const float4*)(Vb + (size_t)(k0 + r) * HDIM + c);
        }
        __syncthreads();

        float s[32];
#pragma unroll
        for (int j = 0; j < 32; ++j) {
            float a = 0.f;
#pragma unroll
            for (int t4 = 0; t4 < 16; ++t4) {
                float4 kk = *(const float4*)&Ks[j][4*t4];   // broadcast LDS
                a += q[4*t4+0]*kk.x + q[4*t4+1]*kk.y
                   + q[4*t4+2]*kk.z + q[4*t4+3]*kk.w;
            }
            s[j] = a * scale;
        }

        float mt = mrun;
#pragma unroll
        for (int j = 0; j < 32; ++j) mt = fmaxf(mt, s[j]);
        float corr = __expf(mrun - mt);
        mrun = mt;
        lrun *= corr;
#pragma unroll
        for (int t = 0; t < 64; ++t) o[t] *= corr;

#pragma unroll
        for (int j = 0; j < 32; ++j) {
            float p = __expf(s[j] - mrun);
            lrun += p;
#pragma unroll
            for (int t4 = 0; t4 < 16; ++t4) {
                float4 vv = *(const float4*)&Vs[j][4*t4];   // broadcast LDS
                o[4*t4+0] += p * vv.x;
                o[4*t4+1] += p * vv.y;
                o[4*t4+2] += p * vv.z;
                o[4*t4+3] += p * vv.w;
            }
        }
    }

    const float inv = 1.f / lrun;
    const int b_ = bh >> 4;
    const int h_ = bh & 15;
    float* Op = g_att + ((size_t)(b_ * SEQ + qi)) * EMB + h_ * HDIM;
#pragma unroll
    for (int t4 = 0; t4 < 16; ++t4) {
        float4 r = make_float4(o[4*t4+0]*inv, o[4*t4+1]*inv,
                               o[4*t4+2]*inv, o[4*t4+3]*inv);
        *(float4*)(Op + 4*t4) = r;
    }
}

// ---------------------------------------------------------------------------
extern "C" void kernel_launch(void* const* d_in, const int* in_sizes, int n_in,
                              void* d_out, int out_size)
{
    const float* x      = (const float*)d_in[0];
    const float* w_qkv  = (const float*)d_in[1];
    const float* b_qkv  = (const float*)d_in[2];
    const float* w_proj = (const float*)d_in[3];
    const float* b_proj = (const float*)d_in[4];
    float* out = (float*)d_out;

    dim3 g1(QKVN / 128, MTOT / 128);     // (24, 64)
    sgemm_nt<0><<<g1, 256>>>(x, w_qkv, b_qkv, nullptr, EMB);

    dim3 g2(SEQ / 128, BATCH * HEADS);   // (16, 64)
    flash_attn<<<g2, 128>>>();

    dim3 g3(EMB / 128, MTOT / 128);      // (8, 64)
    sgemm_nt<1><<<g3, 256>>>(nullptr, w_proj, b_proj, out, EMB);
}

// round 7
// speedup vs baseline: 1.1407x; 1.1407x over previous
#include <cuda_runtime.h>
#include <cstdint>

#define BATCH 4
#define SEQ   2048
#define EMB   1024
#define HEADS 16
#define HDIM  64
#define MTOT  (BATCH*SEQ)      // 8192
#define QKVN  (3*EMB)          // 3072

typedef unsigned long long ull;

// Scratch (static device memory — no allocations allowed)
__device__ float g_q[BATCH*HEADS*SEQ*HDIM];   // 32 MB, [b,h,n,d]
__device__ float g_k[BATCH*HEADS*SEQ*HDIM];
__device__ float g_v[BATCH*HEADS*SEQ*HDIM];
__device__ float g_att[MTOT*EMB];             // 32 MB, [b,n,emb]

// ---------------- packed f32x2 helpers (sm_100a) ----------------------------
__device__ __forceinline__ ull pk2(float lo, float hi) {
    ull r; asm("mov.b64 %0, {%1, %2};" : "=l"(r) : "f"(lo), "f"(hi)); return r;
}
__device__ __forceinline__ void upk2(ull v, float& lo, float& hi) {
    asm("mov.b64 {%0, %1}, %2;" : "=f"(lo), "=f"(hi) : "l"(v));
}
__device__ __forceinline__ ull fma2(ull a, ull b, ull c) {
    ull d; asm("fma.rn.f32x2 %0, %1, %2, %3;" : "=l"(d) : "l"(a), "l"(b), "l"(c));
    return d;
}
__device__ __forceinline__ ull mul2(ull a, ull b) {
    ull d; asm("mul.rn.f32x2 %0, %1, %2;" : "=l"(d) : "l"(a), "l"(b));
    return d;
}

// ---------------------------------------------------------------------------
// Tiled NT SGEMM (round-1 structure, f32x2 inner loop):
// C[M,N] = A[M,K] @ B[N,K]^T + bias
// MODE 0: A = x, B = w_qkv, epilogue scatters into g_q/g_k/g_v ([b,h,n,d])
// MODE 1: A = g_att, B = w_proj, epilogue writes Cout (d_out) with bias
// ---------------------------------------------------------------------------
template<int MODE>
__global__ __launch_bounds__(256)
void sgemm_nt(const float* __restrict__ A, const float* __restrict__ Bm,
              const float* __restrict__ bias, float* __restrict__ Cout, int K)
{
    __shared__ float As[16][132];   // [k][m], padded (132*4=528, 16B-multiple)
    __shared__ float Bs[16][132];   // [k][n]

    const int tid = threadIdx.x;
    const int tx  = tid & 15;       // N dir
    const int ty  = tid >> 4;       // M dir
    const int m0  = blockIdx.y * 128;
    const int n0  = blockIdx.x * 128;

    const float* Aptr = (MODE == 1) ? (const float*)g_att : A;
    const float* Ag = Aptr + (size_t)m0 * K;
    const float* Bg = Bm   + (size_t)n0 * K;

    ull acc2[8][4];                 // 8 rows x 4 col-pairs (fp32x2)
#pragma unroll
    for (int i = 0; i < 8; ++i)
#pragma unroll
        for (int j = 0; j < 4; ++j) acc2[i][j] = 0ull;

    for (int k0 = 0; k0 < K; k0 += 16) {
#pragma unroll
        for (int l = 0; l < 2; ++l) {
            int idx = tid + l * 256;          // 0..511 (float4 index)
            int row = idx >> 2;               // 0..127
            int c4  = (idx & 3) << 2;         // 0,4,8,12
            float4 va = *(const float4*)(Ag + (size_t)row * K + k0 + c4);
            As[c4+0][row] = va.x; As[c4+1][row] = va.y;
            As[c4+2][row] = va.z; As[c4+3][row] = va.w;
            float4 vb = *(const float4*)(Bg + (size_t)row * K + k0 + c4);
            Bs[c4+0][row] = vb.x; Bs[c4+1][row] = vb.y;
            Bs[c4+2][row] = vb.z; Bs[c4+3][row] = vb.w;
        }
        __syncthreads();

#pragma unroll
        for (int kk = 0; kk < 16; ++kk) {
            float a[8];
            *(float4*)&a[0] = *(const float4*)&As[kk][ty*8];
            *(float4*)&a[4] = *(const float4*)&As[kk][ty*8 + 4];
            ulonglong2 bl0 = *(const ulonglong2*)&Bs[kk][tx*8];
            ulonglong2 bl1 = *(const ulonglong2*)&Bs[kk][tx*8 + 4];
            ull b2[4] = { bl0.x, bl0.y, bl1.x, bl1.y };
#pragma unroll
            for (int i = 0; i < 8; ++i) {
                ull as = pk2(a[i], a[i]);
#pragma unroll
                for (int j = 0; j < 4; ++j)
                    acc2[i][j] = fma2(as, b2[j], acc2[i][j]);
            }
        }
        __syncthreads();
    }

    float bv[8];
    *(float4*)&bv[0] = *(const float4*)(bias + n0 + tx*8);
    *(float4*)&bv[4] = *(const float4*)(bias + n0 + tx*8 + 4);

#pragma unroll
    for (int i = 0; i < 8; ++i) {
        float c[8];
        upk2(acc2[i][0], c[0], c[1]);
        upk2(acc2[i][1], c[2], c[3]);
        upk2(acc2[i][2], c[4], c[5]);
        upk2(acc2[i][3], c[6], c[7]);
        float4 r0 = make_float4(c[0]+bv[0], c[1]+bv[1], c[2]+bv[2], c[3]+bv[3]);
        float4 r1 = make_float4(c[4]+bv[4], c[5]+bv[5], c[6]+bv[6], c[7]+bv[7]);

        if (MODE == 1) {
            int m = m0 + ty*8 + i;
            float* p = Cout + (size_t)m * EMB + n0 + tx*8;
            *(float4*)p       = r0;
            *(float4*)(p + 4) = r1;
        } else {
            const int which = n0 >> 10;                 // uniform per block
            float* dst = (which == 0) ? g_q : ((which == 1) ? g_k : g_v);
            const int e  = (n0 + tx*8) & 1023;
            const int h  = e >> 6;
            const int d0 = e & 63;
            int m  = m0 + ty*8 + i;
            int b_ = m >> 11;
            int n_ = m & 2047;
            float* p = dst + (((size_t)(b_*HEADS + h) * SEQ + n_) * HDIM) + d0;
            *(float4*)p       = r0;
            *(float4*)(p + 4) = r1;
        }
    }
}

// ---------------------------------------------------------------------------
// Flash attention (round-1 structure, f32x2 inner loops): one query row per
// thread (q,o packed in f32x2 regs), 32-key SMEM tiles, online softmax.
// Output written in [b, n, emb] layout. grid = (SEQ/128, B*H), block = 128
// ---------------------------------------------------------------------------
__global__ __launch_bounds__(128)
void flash_attn()
{
    const int bh = blockIdx.y;                      // b*16 + h
    const int qi = blockIdx.x * 128 + threadIdx.x;

    const float* Qp = g_q + ((size_t)bh * SEQ + qi) * HDIM;
    const float* Kb = g_k + (size_t)bh * SEQ * HDIM;
    const float* Vb = g_v + (size_t)bh * SEQ * HDIM;

    ull q2[32], o2[32];
    {
        const ulonglong2* Qp2 = (const ulonglong2*)Qp;
#pragma unroll
        for (int i = 0; i < 16; ++i) {
            ulonglong2 t = Qp2[i];
            q2[2*i]   = t.x;
            q2[2*i+1] = t.y;
        }
    }
#pragma unroll
    for (int i = 0; i < 32; ++i) o2[i] = 0ull;

    float mrun = -1e30f, lrun = 0.f;
    const float scale = 0.125f;     // 1/sqrt(64)

    __shared__ float Ks[32][64];    // 8 KB
    __shared__ float Vs[32][64];    // 8 KB

    for (int k0 = 0; k0 < SEQ; k0 += 32) {
        __syncthreads();
#pragma unroll
        for (int l = 0; l < 4; ++l) {
            int idx = threadIdx.x + l * 128;   // 0..511 (float4 idx)
            int r = idx >> 4;                  // 0..31
            int c = (idx & 15) << 2;           // 0..60
            *(float4*)&Ks[r][c] = *(const float4*)(Kb + (size_t)(k0 + r) * HDIM + c);
            *(float4*)&Vs[r][c] = *(const float4*)(Vb + (size_t)(k0 + r) * HDIM + c);
        }
        __syncthreads();

        // S = q . K[j] for 32 keys (packed pairs: kr[t] = dims 4t..4t+3)
        float s[32];
#pragma unroll
        for (int j = 0; j < 32; ++j) {
            ull acc = 0ull;
            const ulonglong2* kr = (const ulonglong2*)&Ks[j][0];  // broadcast
#pragma unroll
            for (int t = 0; t < 16; ++t) {
                ulonglong2 kk = kr[t];                 // floats 4t .. 4t+3
                acc = fma2(q2[2*t],     kk.x, acc);    // dims 4t, 4t+1
                acc = fma2(q2[2*t + 1], kk.y, acc);    // dims 4t+2, 4t+3
            }
            float lo, hi; upk2(acc, lo, hi);
            s[j] = (lo + hi) * scale;
        }

        float mt = mrun;
#pragma unroll
        for (int j = 0; j < 32; ++j) mt = fmaxf(mt, s[j]);
        float corr = __expf(mrun - mt);
        mrun = mt;
        lrun *= corr;
        ull c2 = pk2(corr, corr);
#pragma unroll
        for (int i = 0; i < 32; ++i) o2[i] = mul2(o2[i], c2);

#pragma unroll
        for (int j = 0; j < 32; ++j) {
            float p = __expf(s[j] - mrun);
            lrun += p;
            ull p2 = pk2(p, p);
            const ulonglong2* vr = (const ulonglong2*)&Vs[j][0];  // broadcast
#pragma unroll
            for (int t = 0; t < 16; ++t) {
                ulonglong2 vv = vr[t];                 // floats 4t .. 4t+3
                o2[2*t]     = fma2(p2, vv.x, o2[2*t]);
                o2[2*t + 1] = fma2(p2, vv.y, o2[2*t + 1]);
            }
        }
    }

    const float inv = 1.f / lrun;
    const int b_ = bh >> 4;
    const int h_ = bh & 15;
    float* Op = g_att + ((size_t)(b_ * SEQ + qi)) * EMB + h_ * HDIM;
#pragma unroll
    for (int t = 0; t < 16; ++t) {
        float a, b, c, d;
        upk2(o2[2*t],     a, b);
        upk2(o2[2*t + 1], c, d);
        *(float4*)(Op + 4*t) = make_float4(a*inv, b*inv, c*inv, d*inv);
    }
}

// ---------------------------------------------------------------------------
extern "C" void kernel_launch(void* const* d_in, const int* in_sizes, int n_in,
                              void* d_out, int out_size)
{
    const float* x      = (const float*)d_in[0];
    const float* w_qkv  = (const float*)d_in[1];
    const float* b_qkv  = (const float*)d_in[2];
    const float* w_proj = (const float*)d_in[3];
    const float* b_proj = (const float*)d_in[4];
    float* out = (float*)d_out;

    dim3 g1(QKVN / 128, MTOT / 128);     // (24, 64)
    sgemm_nt<0><<<g1, 256>>>(x, w_qkv, b_qkv, nullptr, EMB);

    dim3 g2(SEQ / 128, BATCH * HEADS);   // (16, 64)
    flash_attn<<<g2, 128>>>();

    dim3 g3(EMB / 128, MTOT / 128);      // (8, 64)
    sgemm_nt<1><<<g3, 256>>>(nullptr, w_proj, b_proj, out, EMB);
}

// round 8
// speedup vs baseline: 1.5667x; 1.3734x over previous
#include <cuda_runtime.h>
#include <cstdint>

#define BATCH 4
#define SEQ   2048
#define EMB   1024
#define HEADS 16
#define HDIM  64
#define MTOT  (BATCH*SEQ)      // 8192
#define QKVN  (3*EMB)          // 3072

typedef unsigned long long ull;

// Scratch (static device memory — no allocations allowed)
__device__ float g_q[BATCH*HEADS*SEQ*HDIM];   // [b,h,n,d]
__device__ float g_k[BATCH*HEADS*SEQ*HDIM];
__device__ float g_v[BATCH*HEADS*SEQ*HDIM];
__device__ float g_att[MTOT*EMB];             // [b,n,emb]

// ---------------- packed f32x2 helpers (sm_100a) ----------------------------
__device__ __forceinline__ ull pk2(float lo, float hi) {
    ull r; asm("mov.b64 %0, {%1, %2};" : "=l"(r) : "f"(lo), "f"(hi)); return r;
}
__device__ __forceinline__ void upk2(ull v, float& lo, float& hi) {
    asm("mov.b64 {%0, %1}, %2;" : "=f"(lo), "=f"(hi) : "l"(v));
}
__device__ __forceinline__ ull fma2(ull a, ull b, ull c) {
    ull d; asm("fma.rn.f32x2 %0, %1, %2, %3;" : "=l"(d) : "l"(a), "l"(b), "l"(c));
    return d;
}
__device__ __forceinline__ ull mul2(ull a, ull b) {
    ull d; asm("mul.rn.f32x2 %0, %1, %2;" : "=l"(d) : "l"(a), "l"(b));
    return d;
}

// ---------------- tf32 helpers ----------------------------------------------
__device__ __forceinline__ uint32_t tf32cvt(float x) {
    uint32_t r; asm("cvt.rna.tf32.f32 %0, %1;" : "=r"(r) : "f"(x)); return r;
}
__device__ __forceinline__ void mma_tf32(float* c, const uint32_t* a, const uint32_t* b) {
    asm volatile("mma.sync.aligned.m16n8k8.row.col.f32.tf32.tf32.f32 "
        "{%0,%1,%2,%3}, {%4,%5,%6,%7}, {%8,%9}, {%0,%1,%2,%3};"
        : "+f"(c[0]), "+f"(c[1]), "+f"(c[2]), "+f"(c[3])
        : "r"(a[0]), "r"(a[1]), "r"(a[2]), "r"(a[3]), "r"(b[0]), "r"(b[1]));
}

// ---------------------------------------------------------------------------
// TF32 tensor-core NT GEMM: C[M,N] = A[M,K] @ B[N,K]^T + bias
// Round-1 single-buffered staging; tf32 conversion at STS time; fragments
// gathered with plain LDS.32 (no ldmatrix, no cp.async, no half).
// MODE 0: A = x, B = w_qkv, epilogue scatters fp32 into g_q/g_k/g_v [b,h,n,d]
// MODE 1: A = g_att, B = w_proj, epilogue writes Cout with bias
// ---------------------------------------------------------------------------
template<int MODE>
__global__ __launch_bounds__(256)
void tgemm(const float* __restrict__ A, const float* __restrict__ Bm,
           const float* __restrict__ bias, float* __restrict__ Cout)
{
    constexpr int K = 1024;
    __shared__ uint32_t As[128 * 20];   // [m][k] tf32, stride 20 (pad 4)
    __shared__ uint32_t Bs[128 * 20];   // [n][k] tf32

    const int tid = threadIdx.x, lane = tid & 31, wid = tid >> 5;
    const int wm = wid & 1, wn = wid >> 1;          // 2 x 4 warp grid
    const int m0 = blockIdx.y * 128, n0 = blockIdx.x * 128;

    const float* Ag = ((MODE == 1) ? (const float*)g_att : A) + (size_t)m0 * K;
    const float* Bg = Bm + (size_t)n0 * K;

    float acc[4][4][4];
#pragma unroll
    for (int i = 0; i < 4; ++i)
#pragma unroll
        for (int j = 0; j < 4; ++j)
#pragma unroll
            for (int r = 0; r < 4; ++r) acc[i][j][r] = 0.f;

    for (int k0 = 0; k0 < K; k0 += 16) {
        __syncthreads();                 // prior-iteration reads done
#pragma unroll
        for (int l = 0; l < 2; ++l) {
            int id  = tid + l * 256;     // 0..511
            int row = id >> 2;           // 0..127
            int c4  = (id & 3) * 4;      // 0,4,8,12
            float4 va = *(const float4*)(Ag + (size_t)row * K + k0 + c4);
            *(uint4*)&As[row * 20 + c4] =
                make_uint4(tf32cvt(va.x), tf32cvt(va.y), tf32cvt(va.z), tf32cvt(va.w));
            float4 vb = *(const float4*)(Bg + (size_t)row * K + k0 + c4);
            *(uint4*)&Bs[row * 20 + c4] =
                make_uint4(tf32cvt(vb.x), tf32cvt(vb.y), tf32cvt(vb.z), tf32cvt(vb.w));
        }
        __syncthreads();

#pragma unroll
        for (int kk = 0; kk < 2; ++kk) {      // two k8 steps
            uint32_t af[4][4], bf[4][2];
#pragma unroll
            for (int mt = 0; mt < 4; ++mt) {
                int r    = wm * 64 + mt * 16 + (lane >> 2);
                int base = r * 20 + kk * 8 + (lane & 3);
                af[mt][0] = As[base];          // (row,   k)
                af[mt][1] = As[base + 160];    // (row+8, k)
                af[mt][2] = As[base + 4];      // (row,   k+4)
                af[mt][3] = As[base + 164];    // (row+8, k+4)
            }
#pragma unroll
            for (int nt = 0; nt < 4; ++nt) {
                int n    = wn * 32 + nt * 8 + (lane >> 2);
                int base = n * 20 + kk * 8 + (lane & 3);
                bf[nt][0] = Bs[base];          // (k,   n)
                bf[nt][1] = Bs[base + 4];      // (k+4, n)
            }
#pragma unroll
            for (int mt = 0; mt < 4; ++mt)
#pragma unroll
                for (int nt = 0; nt < 4; ++nt)
                    mma_tf32(acc[mt][nt], af[mt], bf[nt]);
        }
    }

    // epilogue: c0,c1 = (row, col..col+1), c2,c3 = (row+8, col..col+1)
#pragma unroll
    for (int mt = 0; mt < 4; ++mt) {
#pragma unroll
        for (int nt = 0; nt < 4; ++nt) {
            int row = m0 + wm * 64 + mt * 16 + (lane >> 2);
            int col = n0 + wn * 32 + nt * 8 + (lane & 3) * 2;
            float b0 = bias[col], b1 = bias[col + 1];
            float* a = acc[mt][nt];
            float2 v0 = { a[0] + b0, a[1] + b1 };
            float2 v1 = { a[2] + b0, a[3] + b1 };
            if (MODE == 1) {
                *(float2*)&Cout[(size_t)row * EMB + col] = v0;
                *(float2*)&Cout[(size_t)(row + 8) * EMB + col] = v1;
            } else {
                int which = col >> 10, e = col & 1023, h = e >> 6, d = e & 63;
                float* dst = (which == 0) ? g_q : (which == 1) ? g_k : g_v;
                int b_ = row >> 11;
                size_t base = (size_t)(b_ * HEADS + h) * SEQ;
                *(float2*)&dst[(base + (row & 2047)) * HDIM + d] = v0;
                *(float2*)&dst[(base + ((row + 8) & 2047)) * HDIM + d] = v1;
            }
        }
    }
}

// ---------------------------------------------------------------------------
// Flash attention (round-7 PASSING version, unchanged): one query row per
// thread, f32x2 inner loops, 32-key SMEM tiles, online softmax.
// grid = (SEQ/128, B*H), block = 128
// ---------------------------------------------------------------------------
__global__ __launch_bounds__(128)
void flash_attn()
{
    const int bh = blockIdx.y;                      // b*16 + h
    const int qi = blockIdx.x * 128 + threadIdx.x;

    const float* Qp = g_q + ((size_t)bh * SEQ + qi) * HDIM;
    const float* Kb = g_k + (size_t)bh * SEQ * HDIM;
    const float* Vb = g_v + (size_t)bh * SEQ * HDIM;

    ull q2[32], o2[32];
    {
        const ulonglong2* Qp2 = (const ulonglong2*)Qp;
#pragma unroll
        for (int i = 0; i < 16; ++i) {
            ulonglong2 t = Qp2[i];
            q2[2*i]   = t.x;
            q2[2*i+1] = t.y;
        }
    }
#pragma unroll
    for (int i = 0; i < 32; ++i) o2[i] = 0ull;

    float mrun = -1e30f, lrun = 0.f;
    const float scale = 0.125f;     // 1/sqrt(64)

    __shared__ float Ks[32][64];    // 8 KB
    __shared__ float Vs[32][64];    // 8 KB

    for (int k0 = 0; k0 < SEQ; k0 += 32) {
        __syncthreads();
#pragma unroll
        for (int l = 0; l < 4; ++l) {
            int idx = threadIdx.x + l * 128;   // 0..511 (float4 idx)
            int r = idx >> 4;                  // 0..31
            int c = (idx & 15) << 2;           // 0..60
            *(float4*)&Ks[r][c] = *(const float4*)(Kb + (size_t)(k0 + r) * HDIM + c);
            *(float4*)&Vs[r][c] = *(const float4*)(Vb + (size_t)(k0 + r) * HDIM + c);
        }
        __syncthreads();

        // S = q . K[j] for 32 keys (packed pairs: kr[t] = dims 4t..4t+3)
        float s[32];
#pragma unroll
        for (int j = 0; j < 32; ++j) {
            ull acc = 0ull;
            const ulonglong2* kr = (const ulonglong2*)&Ks[j][0];  // broadcast
#pragma unroll
            for (int t = 0; t < 16; ++t) {
                ulonglong2 kk = kr[t];                 // floats 4t .. 4t+3
                acc = fma2(q2[2*t],     kk.x, acc);    // dims 4t, 4t+1
                acc = fma2(q2[2*t + 1], kk.y, acc);    // dims 4t+2, 4t+3
            }
            float lo, hi; upk2(acc, lo, hi);
            s[j] = (lo + hi) * scale;
        }

        float mt = mrun;
#pragma unroll
        for (int j = 0; j < 32; ++j) mt = fmaxf(mt, s[j]);
        float corr = __expf(mrun - mt);
        mrun = mt;
        lrun *= corr;
        ull c2 = pk2(corr, corr);
#pragma unroll
        for (int i = 0; i < 32; ++i) o2[i] = mul2(o2[i], c2);

#pragma unroll
        for (int j = 0; j < 32; ++j) {
            float p = __expf(s[j] - mrun);
            lrun += p;
            ull p2 = pk2(p, p);
            const ulonglong2* vr = (const ulonglong2*)&Vs[j][0];  // broadcast
#pragma unroll
            for (int t = 0; t < 16; ++t) {
                ulonglong2 vv = vr[t];                 // floats 4t .. 4t+3
                o2[2*t]     = fma2(p2, vv.x, o2[2*t]);
                o2[2*t + 1] = fma2(p2, vv.y, o2[2*t + 1]);
            }
        }
    }

    const float inv = 1.f / lrun;
    const int b_ = bh >> 4;
    const int h_ = bh & 15;
    float* Op = g_att + ((size_t)(b_ * SEQ + qi)) * EMB + h_ * HDIM;
#pragma unroll
    for (int t = 0; t < 16; ++t) {
        float a, b, c, d;
        upk2(o2[2*t],     a, b);
        upk2(o2[2*t + 1], c, d);
        *(float4*)(Op + 4*t) = make_float4(a*inv, b*inv, c*inv, d*inv);
    }
}

// ---------------------------------------------------------------------------
extern "C" void kernel_launch(void* const* d_in, const int* in_sizes, int n_in,
                              void* d_out, int out_size)
{
    const float* x      = (const float*)d_in[0];
    const float* w_qkv  = (const float*)d_in[1];
    const float* b_qkv  = (const float*)d_in[2];
    const float* w_proj = (const float*)d_in[3];
    const float* b_proj = (const float*)d_in[4];
    float* out = (float*)d_out;

    tgemm<0><<<dim3(QKVN / 128, MTOT / 128), 256>>>(x, w_qkv, b_qkv, nullptr);   // (24,64)

    flash_attn<<<dim3(SEQ / 128, BATCH * HEADS), 128>>>();                       // (16,64)

    tgemm<1><<<dim3(EMB / 128, MTOT / 128), 256>>>(nullptr, w_proj, b_proj, out); // (8,64)
}

// round 9
// speedup vs baseline: 3.3447x; 2.1349x over previous
#include <cuda_runtime.h>
#include <cstdint>

#define BATCH 4
#define SEQ   2048
#define EMB   1024
#define HEADS 16
#define HDIM  64
#define MTOT  (BATCH*SEQ)      // 8192
#define QKVN  (3*EMB)          // 3072

// Scratch (static device memory — no allocations allowed)
__device__ float g_q[BATCH*HEADS*SEQ*HDIM];   // [b,h,n,d]
__device__ float g_k[BATCH*HEADS*SEQ*HDIM];
__device__ float g_v[BATCH*HEADS*SEQ*HDIM];
__device__ float g_att[MTOT*EMB];             // [b,n,emb]

// ---------------- tf32 helpers ----------------------------------------------
__device__ __forceinline__ uint32_t tf32cvt(float x) {
    uint32_t r; asm("cvt.rna.tf32.f32 %0, %1;" : "=r"(r) : "f"(x)); return r;
}
__device__ __forceinline__ void mma_tf32(float* c, const uint32_t* a, const uint32_t* b) {
    asm volatile("mma.sync.aligned.m16n8k8.row.col.f32.tf32.tf32.f32 "
        "{%0,%1,%2,%3}, {%4,%5,%6,%7}, {%8,%9}, {%0,%1,%2,%3};"
        : "+f"(c[0]), "+f"(c[1]), "+f"(c[2]), "+f"(c[3])
        : "r"(a[0]), "r"(a[1]), "r"(a[2]), "r"(a[3]), "r"(b[0]), "r"(b[1]));
}
__device__ __forceinline__ float ex2f(float x) {
    float r; asm("ex2.approx.ftz.f32 %0, %1;" : "=f"(r) : "f"(x)); return r;
}

// ---------------------------------------------------------------------------
// TF32 tensor-core NT GEMM (round-8 PASSING version, unchanged):
// C[M,N] = A[M,K] @ B[N,K]^T + bias
// MODE 0: A = x, B = w_qkv, epilogue scatters fp32 into g_q/g_k/g_v [b,h,n,d]
// MODE 1: A = g_att, B = w_proj, epilogue writes Cout with bias
// ---------------------------------------------------------------------------
template<int MODE>
__global__ __launch_bounds__(256)
void tgemm(const float* __restrict__ A, const float* __restrict__ Bm,
           const float* __restrict__ bias, float* __restrict__ Cout)
{
    constexpr int K = 1024;
    __shared__ uint32_t As[128 * 20];   // [m][k] tf32, stride 20 (pad 4)
    __shared__ uint32_t Bs[128 * 20];   // [n][k] tf32

    const int tid = threadIdx.x, lane = tid & 31, wid = tid >> 5;
    const int wm = wid & 1, wn = wid >> 1;          // 2 x 4 warp grid
    const int m0 = blockIdx.y * 128, n0 = blockIdx.x * 128;

    const float* Ag = ((MODE == 1) ? (const float*)g_att : A) + (size_t)m0 * K;
    const float* Bg = Bm + (size_t)n0 * K;

    float acc[4][4][4];
#pragma unroll
    for (int i = 0; i < 4; ++i)
#pragma unroll
        for (int j = 0; j < 4; ++j)
#pragma unroll
            for (int r = 0; r < 4; ++r) acc[i][j][r] = 0.f;

    for (int k0 = 0; k0 < K; k0 += 16) {
        __syncthreads();
#pragma unroll
        for (int l = 0; l < 2; ++l) {
            int id  = tid + l * 256;     // 0..511
            int row = id >> 2;           // 0..127
            int c4  = (id & 3) * 4;      // 0,4,8,12
            float4 va = *(const float4*)(Ag + (size_t)row * K + k0 + c4);
            *(uint4*)&As[row * 20 + c4] =
                make_uint4(tf32cvt(va.x), tf32cvt(va.y), tf32cvt(va.z), tf32cvt(va.w));
            float4 vb = *(const float4*)(Bg + (size_t)row * K + k0 + c4);
            *(uint4*)&Bs[row * 20 + c4] =
                make_uint4(tf32cvt(vb.x), tf32cvt(vb.y), tf32cvt(vb.z), tf32cvt(vb.w));
        }
        __syncthreads();

#pragma unroll
        for (int kk = 0; kk < 2; ++kk) {      // two k8 steps
            uint32_t af[4][4], bf[4][2];
#pragma unroll
            for (int mt = 0; mt < 4; ++mt) {
                int r    = wm * 64 + mt * 16 + (lane >> 2);
                int base = r * 20 + kk * 8 + (lane & 3);
                af[mt][0] = As[base];
                af[mt][1] = As[base + 160];
                af[mt][2] = As[base + 4];
                af[mt][3] = As[base + 164];
            }
#pragma unroll
            for (int nt = 0; nt < 4; ++nt) {
                int n    = wn * 32 + nt * 8 + (lane >> 2);
                int base = n * 20 + kk * 8 + (lane & 3);
                bf[nt][0] = Bs[base];
                bf[nt][1] = Bs[base + 4];
            }
#pragma unroll
            for (int mt = 0; mt < 4; ++mt)
#pragma unroll
                for (int nt = 0; nt < 4; ++nt)
                    mma_tf32(acc[mt][nt], af[mt], bf[nt]);
        }
    }

#pragma unroll
    for (int mt = 0; mt < 4; ++mt) {
#pragma unroll
        for (int nt = 0; nt < 4; ++nt) {
            int row = m0 + wm * 64 + mt * 16 + (lane >> 2);
            int col = n0 + wn * 32 + nt * 8 + (lane & 3) * 2;
            float b0 = bias[col], b1 = bias[col + 1];
            float* a = acc[mt][nt];
            float2 v0 = { a[0] + b0, a[1] + b1 };
            float2 v1 = { a[2] + b0, a[3] + b1 };
            if (MODE == 1) {
                *(float2*)&Cout[(size_t)row * EMB + col] = v0;
                *(float2*)&Cout[(size_t)(row + 8) * EMB + col] = v1;
            } else {
                int which = col >> 10, e = col & 1023, h = e >> 6, d = e & 63;
                float* dst = (which == 0) ? g_q : (which == 1) ? g_k : g_v;
                int b_ = row >> 11;
                size_t base = (size_t)(b_ * HEADS + h) * SEQ;
                *(float2*)&dst[(base + (row & 2047)) * HDIM + d] = v0;
                *(float2*)&dst[(base + ((row + 8) & 2047)) * HDIM + d] = v1;
            }
        }
    }
}

// ---------------------------------------------------------------------------
// TF32 tensor-core flash attention.
// grid (SEQ/128, BATCH*HEADS), 256 threads = 8 warps x 16 query rows.
// Same proven style as tgemm: smem staging with tf32cvt at STS, plain LDS.32
// fragment gathers, no cp.async / ldmatrix / half.
//   Ks: [64 keys][68]  (68 = 4*17 -> conflict-free for row=lane>>2 pattern)
//   Vs: [64 keys][72]  (72 -> banks 8k+d, conflict-free for row=lane&3 pattern)
//   Q staged through the same buffer once; Q fragments live in registers.
// ---------------------------------------------------------------------------
__global__ __launch_bounds__(256)
void fattn_tc()
{
    __shared__ uint32_t smem[8960];          // 35 KB
    uint32_t* Ks = smem;                     // 64*68 = 4352 words
    uint32_t* Vs = smem + 4352;              // 64*72 = 4608 words

    const int tid = threadIdx.x, lane = tid & 31, wid = tid >> 5;
    const int bh = blockIdx.y, q0 = blockIdx.x * 128;

    const float* Qg = g_q + ((size_t)bh * SEQ + q0) * HDIM;
    const float* Kg = g_k + (size_t)bh * SEQ * HDIM;
    const float* Vg = g_v + (size_t)bh * SEQ * HDIM;

    // ---- stage Q (128 x 64) as tf32, stride 68; then lift fragments to regs
#pragma unroll
    for (int l = 0; l < 8; ++l) {
        int id = tid + l * 256;              // 0..2047 (float4 chunks)
        int row = id >> 4, c4 = (id & 15) * 4;
        float4 v = *(const float4*)(Qg + row * HDIM + c4);
        *(uint4*)&smem[row * 68 + c4] =
            make_uint4(tf32cvt(v.x), tf32cvt(v.y), tf32cvt(v.z), tf32cvt(v.w));
    }
    __syncthreads();

    uint32_t qf[8][4];
    {
        int r = wid * 16 + (lane >> 2);
        int j = lane & 3;
#pragma unroll
        for (int ks = 0; ks < 8; ++ks) {
            int base = r * 68 + ks * 8 + j;
            qf[ks][0] = smem[base];              // (r,   k)
            qf[ks][1] = smem[base + 8 * 68];     // (r+8, k)
            qf[ks][2] = smem[base + 4];          // (r,   k+4)
            qf[ks][3] = smem[base + 8 * 68 + 4]; // (r+8, k+4)
        }
    }
    __syncthreads();

    float oacc[8][4];
#pragma unroll
    for (int i = 0; i < 8; ++i)
#pragma unroll
        for (int r = 0; r < 4; ++r) oacc[i][r] = 0.f;
    float mrun0 = -1e30f, mrun1 = -1e30f;
    float lrun0 = 0.f, lrun1 = 0.f;          // per-thread partial row sums
    const float C2 = 0.18033688f;            // log2(e) / sqrt(64)

    for (int t = 0; t < SEQ / 64; ++t) {
        // ---- load K,V tile (64 x 64 each) as tf32
        const float* Kt = Kg + (size_t)t * 64 * HDIM;
        const float* Vt = Vg + (size_t)t * 64 * HDIM;
#pragma unroll
        for (int l = 0; l < 4; ++l) {
            int id = tid + l * 256;          // 0..1023
            int row = id >> 4, c4 = (id & 15) * 4;
            float4 a = *(const float4*)(Kt + row * HDIM + c4);
            *(uint4*)&Ks[row * 68 + c4] =
                make_uint4(tf32cvt(a.x), tf32cvt(a.y), tf32cvt(a.z), tf32cvt(a.w));
            float4 b = *(const float4*)(Vt + row * HDIM + c4);
            *(uint4*)&Vs[row * 72 + c4] =
                make_uint4(tf32cvt(b.x), tf32cvt(b.y), tf32cvt(b.z), tf32cvt(b.w));
        }
        __syncthreads();

        // ---- S = Q K^T : per warp 16 x 64, D-fragments sacc[nt]
        float sacc[8][4];
#pragma unroll
        for (int i = 0; i < 8; ++i)
#pragma unroll
            for (int r = 0; r < 4; ++r) sacc[i][r] = 0.f;
#pragma unroll
        for (int nt = 0; nt < 8; ++nt) {
            int n = nt * 8 + (lane >> 2);
#pragma unroll
            for (int ks = 0; ks < 8; ++ks) {
                int base = n * 68 + ks * 8 + (lane & 3);
                uint32_t bf[2] = { Ks[base], Ks[base + 4] };   // (k,n),(k+4,n)
                mma_tf32(sacc[nt], qf[ks], bf);
            }
        }

        // ---- online softmax (raw scores; scale folded into C2)
        float mx0 = -1e30f, mx1 = -1e30f;
#pragma unroll
        for (int i = 0; i < 8; ++i) {
            mx0 = fmaxf(mx0, fmaxf(sacc[i][0], sacc[i][1]));
            mx1 = fmaxf(mx1, fmaxf(sacc[i][2], sacc[i][3]));
        }
        mx0 = fmaxf(mx0, __shfl_xor_sync(0xffffffffu, mx0, 1));
        mx0 = fmaxf(mx0, __shfl_xor_sync(0xffffffffu, mx0, 2));
        mx1 = fmaxf(mx1, __shfl_xor_sync(0xffffffffu, mx1, 1));
        mx1 = fmaxf(mx1, __shfl_xor_sync(0xffffffffu, mx1, 2));
        float mn0 = fmaxf(mrun0, mx0), mn1 = fmaxf(mrun1, mx1);
        float c0 = ex2f((mrun0 - mn0) * C2), c1 = ex2f((mrun1 - mn1) * C2);
        mrun0 = mn0; mrun1 = mn1;
#pragma unroll
        for (int i = 0; i < 8; ++i) {
            oacc[i][0] *= c0; oacc[i][1] *= c0;
            oacc[i][2] *= c1; oacc[i][3] *= c1;
        }
        lrun0 *= c0; lrun1 *= c1;

        // ---- exp, re-fragment P (D-layout -> A-layout), PV accumulate
        // D owns cols {2j, 2j+1}; A needs cols {j, j+4}. Col c is owned by the
        // quad-mate with lane&3 = c>>1 in slot c&1.
        const int j = lane & 3;
        const int src_lo = (lane & ~3) | (j >> 1);       // col j
        const int src_hi = src_lo + 2;                   // col j+4
        const bool odd = (j & 1) != 0;
#pragma unroll
        for (int kt = 0; kt < 8; ++kt) {
            float p0 = ex2f((sacc[kt][0] - mn0) * C2);
            float p1 = ex2f((sacc[kt][1] - mn0) * C2);
            float p2 = ex2f((sacc[kt][2] - mn1) * C2);
            float p3 = ex2f((sacc[kt][3] - mn1) * C2);
            lrun0 += p0 + p1;
            lrun1 += p2 + p3;

            float t0 = __shfl_sync(0xffffffffu, p0, src_lo);
            float t1 = __shfl_sync(0xffffffffu, p1, src_lo);
            float t2 = __shfl_sync(0xffffffffu, p2, src_lo);
            float t3 = __shfl_sync(0xffffffffu, p3, src_lo);
            float u0 = __shfl_sync(0xffffffffu, p0, src_hi);
            float u1 = __shfl_sync(0xffffffffu, p1, src_hi);
            float u2 = __shfl_sync(0xffffffffu, p2, src_hi);
            float u3 = __shfl_sync(0xffffffffu, p3, src_hi);

            uint32_t pa[4];
            pa[0] = tf32cvt(odd ? t1 : t0);   // P(r,   kt*8 + j)
            pa[1] = tf32cvt(odd ? t3 : t2);   // P(r+8, kt*8 + j)
            pa[2] = tf32cvt(odd ? u1 : u0);   // P(r,   kt*8 + j+4)
            pa[3] = tf32cvt(odd ? u3 : u2);   // P(r+8, kt*8 + j+4)

#pragma unroll
            for (int nt = 0; nt < 8; ++nt) {
                int base = (kt * 8 + j) * 72 + nt * 8 + (lane >> 2);
                uint32_t vf[2] = { Vs[base], Vs[base + 4 * 72] };  // V(k,n),V(k+4,n)
                mma_tf32(oacc[nt], pa, vf);
            }
        }
        __syncthreads();
    }

    // ---- epilogue: quad-reduce l, normalize, store [b, n, emb]
    lrun0 += __shfl_xor_sync(0xffffffffu, lrun0, 1);
    lrun0 += __shfl_xor_sync(0xffffffffu, lrun0, 2);
    lrun1 += __shfl_xor_sync(0xffffffffu, lrun1, 1);
    lrun1 += __shfl_xor_sync(0xffffffffu, lrun1, 2);
    float inv0 = 1.f / lrun0;
    float inv1 = 1.f / lrun1;

    int b_ = bh >> 4, h = bh & 15;
    int row = q0 + wid * 16 + (lane >> 2);
    size_t base0 = ((size_t)b_ * SEQ + row) * EMB + h * HDIM;
    size_t base1 = base0 + (size_t)8 * EMB;
#pragma unroll
    for (int nt = 0; nt < 8; ++nt) {
        int d = nt * 8 + (lane & 3) * 2;
        *(float2*)&g_att[base0 + d] = make_float2(oacc[nt][0] * inv0, oacc[nt][1] * inv0);
        *(float2*)&g_att[base1 + d] = make_float2(oacc[nt][2] * inv1, oacc[nt][3] * inv1);
    }
}

// ---------------------------------------------------------------------------
extern "C" void kernel_launch(void* const* d_in, const int* in_sizes, int n_in,
                              void* d_out, int out_size)
{
    const float* x      = (const float*)d_in[0];
    const float* w_qkv  = (const float*)d_in[1];
    const float* b_qkv  = (const float*)d_in[2];
    const float* w_proj = (const float*)d_in[3];
    const float* b_proj = (const float*)d_in[4];
    float* out = (float*)d_out;

    tgemm<0><<<dim3(QKVN / 128, MTOT / 128), 256>>>(x, w_qkv, b_qkv, nullptr);    // (24,64)

    fattn_tc<<<dim3(SEQ / 128, BATCH * HEADS), 256>>>();                          // (16,64)

    tgemm<1><<<dim3(EMB / 128, MTOT / 128), 256>>>(nullptr, w_proj, b_proj, out); // (8,64)
}

// round 10
// speedup vs baseline: 3.4889x; 1.0431x over previous
#include <cuda_runtime.h>
#include <cstdint>

#define BATCH 4
#define SEQ   2048
#define EMB   1024
#define HEADS 16
#define HDIM  64
#define MTOT  (BATCH*SEQ)      // 8192
#define QKVN  (3*EMB)          // 3072

// Scratch (static device memory — no allocations allowed)
__device__ float g_q[BATCH*HEADS*SEQ*HDIM];   // [b,h,n,d]
__device__ float g_k[BATCH*HEADS*SEQ*HDIM];
__device__ float g_v[BATCH*HEADS*SEQ*HDIM];
__device__ float g_att[MTOT*EMB];             // [b,n,emb]

// ---------------- tf32 helpers ----------------------------------------------
__device__ __forceinline__ uint32_t tf32cvt(float x) {
    uint32_t r; asm("cvt.rna.tf32.f32 %0, %1;" : "=r"(r) : "f"(x)); return r;
}
__device__ __forceinline__ void mma_tf32(float* c, const uint32_t* a, const uint32_t* b) {
    asm volatile("mma.sync.aligned.m16n8k8.row.col.f32.tf32.tf32.f32 "
        "{%0,%1,%2,%3}, {%4,%5,%6,%7}, {%8,%9}, {%0,%1,%2,%3};"
        : "+f"(c[0]), "+f"(c[1]), "+f"(c[2]), "+f"(c[3])
        : "r"(a[0]), "r"(a[1]), "r"(a[2]), "r"(a[3]), "r"(b[0]), "r"(b[1]));
}
__device__ __forceinline__ float ex2f(float x) {
    float r; asm("ex2.approx.ftz.f32 %0, %1;" : "=f"(r) : "f"(x)); return r;
}

// ---------------------------------------------------------------------------
// TF32 tensor-core NT GEMM, double-buffered + register-prefetch pipeline:
// C[M,N] = A[M,K] @ B[N,K]^T + bias
// MODE 0: A = x, B = w_qkv, epilogue scatters fp32 into g_q/g_k/g_v [b,h,n,d]
// MODE 1: A = g_att, B = w_proj, epilogue writes Cout with bias
// ---------------------------------------------------------------------------
template<int MODE>
__global__ __launch_bounds__(256, 2)
void tgemm(const float* __restrict__ A, const float* __restrict__ Bm,
           const float* __restrict__ bias, float* __restrict__ Cout)
{
    constexpr int K = 1024;
    constexpr int NIT = K / 16;
    __shared__ uint32_t As[2][128 * 20];   // [m][k] tf32, stride 20 (pad 4)
    __shared__ uint32_t Bs[2][128 * 20];   // [n][k] tf32

    const int tid = threadIdx.x, lane = tid & 31, wid = tid >> 5;
    const int wm = wid & 1, wn = wid >> 1;          // 2 x 4 warp grid
    const int m0 = blockIdx.y * 128, n0 = blockIdx.x * 128;

    const float* Ag = ((MODE == 1) ? (const float*)g_att : A) + (size_t)m0 * K;
    const float* Bg = Bm + (size_t)n0 * K;

    // per-thread staging coords (2 chunks per tensor)
    const int r0 = tid >> 2,        c0 = (tid & 3) * 4;
    const int r1 = (tid + 256) >> 2, c1 = c0;       // second chunk: row + 64

    float4 pva[2], pvb[2];                          // prefetch registers
    auto ldg = [&](int k0) {
        pva[0] = *(const float4*)(Ag + (size_t)r0 * K + k0 + c0);
        pvb[0] = *(const float4*)(Bg + (size_t)r0 * K + k0 + c0);
        pva[1] = *(const float4*)(Ag + (size_t)r1 * K + k0 + c1);
        pvb[1] = *(const float4*)(Bg + (size_t)r1 * K + k0 + c1);
    };
    auto sts = [&](int st) {
        *(uint4*)&As[st][r0 * 20 + c0] =
            make_uint4(tf32cvt(pva[0].x), tf32cvt(pva[0].y), tf32cvt(pva[0].z), tf32cvt(pva[0].w));
        *(uint4*)&Bs[st][r0 * 20 + c0] =
            make_uint4(tf32cvt(pvb[0].x), tf32cvt(pvb[0].y), tf32cvt(pvb[0].z), tf32cvt(pvb[0].w));
        *(uint4*)&As[st][r1 * 20 + c1] =
            make_uint4(tf32cvt(pva[1].x), tf32cvt(pva[1].y), tf32cvt(pva[1].z), tf32cvt(pva[1].w));
        *(uint4*)&Bs[st][r1 * 20 + c1] =
            make_uint4(tf32cvt(pvb[1].x), tf32cvt(pvb[1].y), tf32cvt(pvb[1].z), tf32cvt(pvb[1].w));
    };

    float acc[4][4][4];
#pragma unroll
    for (int i = 0; i < 4; ++i)
#pragma unroll
        for (int j = 0; j < 4; ++j)
#pragma unroll
            for (int r = 0; r < 4; ++r) acc[i][j][r] = 0.f;

    ldg(0); sts(0);
    __syncthreads();

    for (int it = 0; it < NIT; ++it) {
        if (it + 1 < NIT) ldg((it + 1) * 16);       // overlaps with mma below
        const int cur = it & 1;
        const uint32_t* Ac = As[cur];
        const uint32_t* Bc = Bs[cur];

#pragma unroll
        for (int kk = 0; kk < 2; ++kk) {            // two k8 steps
            uint32_t af[4][4], bf[4][2];
#pragma unroll
            for (int mt = 0; mt < 4; ++mt) {
                int r    = wm * 64 + mt * 16 + (lane >> 2);
                int base = r * 20 + kk * 8 + (lane & 3);
                af[mt][0] = Ac[base];
                af[mt][1] = Ac[base + 160];
                af[mt][2] = Ac[base + 4];
                af[mt][3] = Ac[base + 164];
            }
#pragma unroll
            for (int nt = 0; nt < 4; ++nt) {
                int n    = wn * 32 + nt * 8 + (lane >> 2);
                int base = n * 20 + kk * 8 + (lane & 3);
                bf[nt][0] = Bc[base];
                bf[nt][1] = Bc[base + 4];
            }
#pragma unroll
            for (int mt = 0; mt < 4; ++mt)
#pragma unroll
                for (int nt = 0; nt < 4; ++nt)
                    mma_tf32(acc[mt][nt], af[mt], bf[nt]);
        }

        if (it + 1 < NIT) sts((it + 1) & 1);
        __syncthreads();
    }

#pragma unroll
    for (int mt = 0; mt < 4; ++mt) {
#pragma unroll
        for (int nt = 0; nt < 4; ++nt) {
            int row = m0 + wm * 64 + mt * 16 + (lane >> 2);
            int col = n0 + wn * 32 + nt * 8 + (lane & 3) * 2;
            float b0 = bias[col], b1 = bias[col + 1];
            float* a = acc[mt][nt];
            float2 v0 = { a[0] + b0, a[1] + b1 };
            float2 v1 = { a[2] + b0, a[3] + b1 };
            if (MODE == 1) {
                *(float2*)&Cout[(size_t)row * EMB + col] = v0;
                *(float2*)&Cout[(size_t)(row + 8) * EMB + col] = v1;
            } else {
                int which = col >> 10, e = col & 1023, h = e >> 6, d = e & 63;
                float* dst = (which == 0) ? g_q : (which == 1) ? g_k : g_v;
                int b_ = row >> 11;
                size_t base = (size_t)(b_ * HEADS + h) * SEQ;
                *(float2*)&dst[(base + (row & 2047)) * HDIM + d] = v0;
                *(float2*)&dst[(base + ((row + 8) & 2047)) * HDIM + d] = v1;
            }
        }
    }
}

// ---------------------------------------------------------------------------
// TF32 tensor-core flash attention (round-9 PASSING version, unchanged).
// grid (SEQ/128, BATCH*HEADS), 256 threads = 8 warps x 16 query rows.
// ---------------------------------------------------------------------------
__global__ __launch_bounds__(256)
void fattn_tc()
{
    __shared__ uint32_t smem[8960];          // 35 KB
    uint32_t* Ks = smem;                     // 64*68 = 4352 words
    uint32_t* Vs = smem + 4352;              // 64*72 = 4608 words

    const int tid = threadIdx.x, lane = tid & 31, wid = tid >> 5;
    const int bh = blockIdx.y, q0 = blockIdx.x * 128;

    const float* Qg = g_q + ((size_t)bh * SEQ + q0) * HDIM;
    const float* Kg = g_k + (size_t)bh * SEQ * HDIM;
    const float* Vg = g_v + (size_t)bh * SEQ * HDIM;

    // ---- stage Q (128 x 64) as tf32, stride 68; then lift fragments to regs
#pragma unroll
    for (int l = 0; l < 8; ++l) {
        int id = tid + l * 256;              // 0..2047 (float4 chunks)
        int row = id >> 4, c4 = (id & 15) * 4;
        float4 v = *(const float4*)(Qg + row * HDIM + c4);
        *(uint4*)&smem[row * 68 + c4] =
            make_uint4(tf32cvt(v.x), tf32cvt(v.y), tf32cvt(v.z), tf32cvt(v.w));
    }
    __syncthreads();

    uint32_t qf[8][4];
    {
        int r = wid * 16 + (lane >> 2);
        int j = lane & 3;
#pragma unroll
        for (int ks = 0; ks < 8; ++ks) {
            int base = r * 68 + ks * 8 + j;
            qf[ks][0] = smem[base];              // (r,   k)
            qf[ks][1] = smem[base + 8 * 68];     // (r+8, k)
            qf[ks][2] = smem[base + 4];          // (r,   k+4)
            qf[ks][3] = smem[base + 8 * 68 + 4]; // (r+8, k+4)
        }
    }
    __syncthreads();

    float oacc[8][4];
#pragma unroll
    for (int i = 0; i < 8; ++i)
#pragma unroll
        for (int r = 0; r < 4; ++r) oacc[i][r] = 0.f;
    float mrun0 = -1e30f, mrun1 = -1e30f;
    float lrun0 = 0.f, lrun1 = 0.f;          // per-thread partial row sums
    const float C2 = 0.18033688f;            // log2(e) / sqrt(64)

    for (int t = 0; t < SEQ / 64; ++t) {
        // ---- load K,V tile (64 x 64 each) as tf32
        const float* Kt = Kg + (size_t)t * 64 * HDIM;
        const float* Vt = Vg + (size_t)t * 64 * HDIM;
#pragma unroll
        for (int l = 0; l < 4; ++l) {
            int id = tid + l * 256;          // 0..1023
            int row = id >> 4, c4 = (id & 15) * 4;
            float4 a = *(const float4*)(Kt + row * HDIM + c4);
            *(uint4*)&Ks[row * 68 + c4] =
                make_uint4(tf32cvt(a.x), tf32cvt(a.y), tf32cvt(a.z), tf32cvt(a.w));
            float4 b = *(const float4*)(Vt + row * HDIM + c4);
            *(uint4*)&Vs[row * 72 + c4] =
                make_uint4(tf32cvt(b.x), tf32cvt(b.y), tf32cvt(b.z), tf32cvt(b.w));
        }
        __syncthreads();

        // ---- S = Q K^T : per warp 16 x 64, D-fragments sacc[nt]
        float sacc[8][4];
#pragma unroll
        for (int i = 0; i < 8; ++i)
#pragma unroll
            for (int r = 0; r < 4; ++r) sacc[i][r] = 0.f;
#pragma unroll
        for (int nt = 0; nt < 8; ++nt) {
            int n = nt * 8 + (lane >> 2);
#pragma unroll
            for (int ks = 0; ks < 8; ++ks) {
                int base = n * 68 + ks * 8 + (lane & 3);
                uint32_t bf[2] = { Ks[base], Ks[base + 4] };   // (k,n),(k+4,n)
                mma_tf32(sacc[nt], qf[ks], bf);
            }
        }

        // ---- online softmax (raw scores; scale folded into C2)
        float mx0 = -1e30f, mx1 = -1e30f;
#pragma unroll
        for (int i = 0; i < 8; ++i) {
            mx0 = fmaxf(mx0, fmaxf(sacc[i][0], sacc[i][1]));
            mx1 = fmaxf(mx1, fmaxf(sacc[i][2], sacc[i][3]));
        }
        mx0 = fmaxf(mx0, __shfl_xor_sync(0xffffffffu, mx0, 1));
        mx0 = fmaxf(mx0, __shfl_xor_sync(0xffffffffu, mx0, 2));
        mx1 = fmaxf(mx1, __shfl_xor_sync(0xffffffffu, mx1, 1));
        mx1 = fmaxf(mx1, __shfl_xor_sync(0xffffffffu, mx1, 2));
        float mn0 = fmaxf(mrun0, mx0), mn1 = fmaxf(mrun1, mx1);
        float c0 = ex2f((mrun0 - mn0) * C2), c1 = ex2f((mrun1 - mn1) * C2);
        mrun0 = mn0; mrun1 = mn1;
#pragma unroll
        for (int i = 0; i < 8; ++i) {
            oacc[i][0] *= c0; oacc[i][1] *= c0;
            oacc[i][2] *= c1; oacc[i][3] *= c1;
        }
        lrun0 *= c0; lrun1 *= c1;

        // ---- exp, re-fragment P (D-layout -> A-layout), PV accumulate
        const int j = lane & 3;
        const int src_lo = (lane & ~3) | (j >> 1);       // col j
        const int src_hi = src_lo + 2;                   // col j+4
        const bool odd = (j & 1) != 0;
#pragma unroll
        for (int kt = 0; kt < 8; ++kt) {
            float p0 = ex2f((sacc[kt][0] - mn0) * C2);
            float p1 = ex2f((sacc[kt][1] - mn0) * C2);
            float p2 = ex2f((sacc[kt][2] - mn1) * C2);
            float p3 = ex2f((sacc[kt][3] - mn1) * C2);
            lrun0 += p0 + p1;
            lrun1 += p2 + p3;

            float t0 = __shfl_sync(0xffffffffu, p0, src_lo);
            float t1 = __shfl_sync(0xffffffffu, p1, src_lo);
            float t2 = __shfl_sync(0xffffffffu, p2, src_lo);
            float t3 = __shfl_sync(0xffffffffu, p3, src_lo);
            float u0 = __shfl_sync(0xffffffffu, p0, src_hi);
            float u1 = __shfl_sync(0xffffffffu, p1, src_hi);
            float u2 = __shfl_sync(0xffffffffu, p2, src_hi);
            float u3 = __shfl_sync(0xffffffffu, p3, src_hi);

            uint32_t pa[4];
            pa[0] = tf32cvt(odd ? t1 : t0);   // P(r,   kt*8 + j)
            pa[1] = tf32cvt(odd ? t3 : t2);   // P(r+8, kt*8 + j)
            pa[2] = tf32cvt(odd ? u1 : u0);   // P(r,   kt*8 + j+4)
            pa[3] = tf32cvt(odd ? u3 : u2);   // P(r+8, kt*8 + j+4)

#pragma unroll
            for (int nt = 0; nt < 8; ++nt) {
                int base = (kt * 8 + j) * 72 + nt * 8 + (lane >> 2);
                uint32_t vf[2] = { Vs[base], Vs[base + 4 * 72] };  // V(k,n),V(k+4,n)
                mma_tf32(oacc[nt], pa, vf);
            }
        }
        __syncthreads();
    }

    // ---- epilogue: quad-reduce l, normalize, store [b, n, emb]
    lrun0 += __shfl_xor_sync(0xffffffffu, lrun0, 1);
    lrun0 += __shfl_xor_sync(0xffffffffu, lrun0, 2);
    lrun1 += __shfl_xor_sync(0xffffffffu, lrun1, 1);
    lrun1 += __shfl_xor_sync(0xffffffffu, lrun1, 2);
    float inv0 = 1.f / lrun0;
    float inv1 = 1.f / lrun1;

    int b_ = bh >> 4, h = bh & 15;
    int row = q0 + wid * 16 + (lane >> 2);
    size_t base0 = ((size_t)b_ * SEQ + row) * EMB + h * HDIM;
    size_t base1 = base0 + (size_t)8 * EMB;
#pragma unroll
    for (int nt = 0; nt < 8; ++nt) {
        int d = nt * 8 + (lane & 3) * 2;
        *(float2*)&g_att[base0 + d] = make_float2(oacc[nt][0] * inv0, oacc[nt][1] * inv0);
        *(float2*)&g_att[base1 + d] = make_float2(oacc[nt][2] * inv1, oacc[nt][3] * inv1);
    }
}

// ---------------------------------------------------------------------------
extern "C" void kernel_launch(void* const* d_in, const int* in_sizes, int n_in,
                              void* d_out, int out_size)
{
    const float* x      = (const float*)d_in[0];
    const float* w_qkv  = (const float*)d_in[1];
    const float* b_qkv  = (const float*)d_in[2];
    const float* w_proj = (const float*)d_in[3];
    const float* b_proj = (const float*)d_in[4];
    float* out = (float*)d_out;

    tgemm<0><<<dim3(QKVN / 128, MTOT / 128), 256>>>(x, w_qkv, b_qkv, nullptr);    // (24,64)

    fattn_tc<<<dim3(SEQ / 128, BATCH * HEADS), 256>>>();                          // (16,64)

    tgemm<1><<<dim3(EMB / 128, MTOT / 128), 256>>>(nullptr, w_proj, b_proj, out); // (8,64)
}

// round 11
// speedup vs baseline: 4.7666x; 1.3662x over previous
#include <cuda_runtime.h>
#include <cstdint>

#define BATCH 4
#define SEQ   2048
#define EMB   1024
#define HEADS 16
#define HDIM  64
#define MTOT  (BATCH*SEQ)      // 8192
#define QKVN  (3*EMB)          // 3072

// Scratch (static device memory — no allocations allowed)
__device__ float g_q[BATCH*HEADS*SEQ*HDIM];   // [b,h,n,d]
__device__ float g_k[BATCH*HEADS*SEQ*HDIM];
__device__ float g_v[BATCH*HEADS*SEQ*HDIM];
__device__ float g_att[MTOT*EMB];             // [b,n,emb]

// ---------------- tf32 helpers ----------------------------------------------
__device__ __forceinline__ uint32_t tf32cvt(float x) {
    uint32_t r; asm("cvt.rna.tf32.f32 %0, %1;" : "=r"(r) : "f"(x)); return r;
}
__device__ __forceinline__ void mma_tf32(float* c, const uint32_t* a, const uint32_t* b) {
    asm volatile("mma.sync.aligned.m16n8k8.row.col.f32.tf32.tf32.f32 "
        "{%0,%1,%2,%3}, {%4,%5,%6,%7}, {%8,%9}, {%0,%1,%2,%3};"
        : "+f"(c[0]), "+f"(c[1]), "+f"(c[2]), "+f"(c[3])
        : "r"(a[0]), "r"(a[1]), "r"(a[2]), "r"(a[3]), "r"(b[0]), "r"(b[1]));
}
__device__ __forceinline__ float ex2f(float x) {
    float r; asm("ex2.approx.ftz.f32 %0, %1;" : "=f"(r) : "f"(x)); return r;
}
// pack two fp32 -> f16x2 word: low half = lo, high half = hi (first src = high)
__device__ __forceinline__ uint32_t h2pk(float lo, float hi) {
    uint32_t r; asm("cvt.rn.f16x2.f32 %0, %1, %2;" : "=r"(r) : "f"(hi), "f"(lo));
    return r;
}
// fp16 mma, fp32 accumulate
__device__ __forceinline__ void mma_f16(float* c, const uint32_t* a, const uint32_t* b) {
    asm volatile("mma.sync.aligned.m16n8k16.row.col.f32.f16.f16.f32 "
        "{%0,%1,%2,%3}, {%4,%5,%6,%7}, {%8,%9}, {%0,%1,%2,%3};"
        : "+f"(c[0]), "+f"(c[1]), "+f"(c[2]), "+f"(c[3])
        : "r"(a[0]), "r"(a[1]), "r"(a[2]), "r"(a[3]), "r"(b[0]), "r"(b[1]));
}

// ---------------------------------------------------------------------------
// TF32 tensor-core NT GEMM (round-10 PASSING version, unchanged):
// double-buffered + register-prefetch pipeline.
// MODE 0: A = x, B = w_qkv, epilogue scatters fp32 into g_q/g_k/g_v [b,h,n,d]
// MODE 1: A = g_att, B = w_proj, epilogue writes Cout with bias
// ---------------------------------------------------------------------------
template<int MODE>
__global__ __launch_bounds__(256, 2)
void tgemm(const float* __restrict__ A, const float* __restrict__ Bm,
           const float* __restrict__ bias, float* __restrict__ Cout)
{
    constexpr int K = 1024;
    constexpr int NIT = K / 16;
    __shared__ uint32_t As[2][128 * 20];   // [m][k] tf32, stride 20 (pad 4)
    __shared__ uint32_t Bs[2][128 * 20];   // [n][k] tf32

    const int tid = threadIdx.x, lane = tid & 31, wid = tid >> 5;
    const int wm = wid & 1, wn = wid >> 1;          // 2 x 4 warp grid
    const int m0 = blockIdx.y * 128, n0 = blockIdx.x * 128;

    const float* Ag = ((MODE == 1) ? (const float*)g_att : A) + (size_t)m0 * K;
    const float* Bg = Bm + (size_t)n0 * K;

    const int r0 = tid >> 2,         c0 = (tid & 3) * 4;
    const int r1 = (tid + 256) >> 2, c1 = c0;

    float4 pva[2], pvb[2];
    auto ldg = [&](int k0) {
        pva[0] = *(const float4*)(Ag + (size_t)r0 * K + k0 + c0);
        pvb[0] = *(const float4*)(Bg + (size_t)r0 * K + k0 + c0);
        pva[1] = *(const float4*)(Ag + (size_t)r1 * K + k0 + c1);
        pvb[1] = *(const float4*)(Bg + (size_t)r1 * K + k0 + c1);
    };
    auto sts = [&](int st) {
        *(uint4*)&As[st][r0 * 20 + c0] =
            make_uint4(tf32cvt(pva[0].x), tf32cvt(pva[0].y), tf32cvt(pva[0].z), tf32cvt(pva[0].w));
        *(uint4*)&Bs[st][r0 * 20 + c0] =
            make_uint4(tf32cvt(pvb[0].x), tf32cvt(pvb[0].y), tf32cvt(pvb[0].z), tf32cvt(pvb[0].w));
        *(uint4*)&As[st][r1 * 20 + c1] =
            make_uint4(tf32cvt(pva[1].x), tf32cvt(pva[1].y), tf32cvt(pva[1].z), tf32cvt(pva[1].w));
        *(uint4*)&Bs[st][r1 * 20 + c1] =
            make_uint4(tf32cvt(pvb[1].x), tf32cvt(pvb[1].y), tf32cvt(pvb[1].z), tf32cvt(pvb[1].w));
    };

    float acc[4][4][4];
#pragma unroll
    for (int i = 0; i < 4; ++i)
#pragma unroll
        for (int j = 0; j < 4; ++j)
#pragma unroll
            for (int r = 0; r < 4; ++r) acc[i][j][r] = 0.f;

    ldg(0); sts(0);
    __syncthreads();

    for (int it = 0; it < NIT; ++it) {
        if (it + 1 < NIT) ldg((it + 1) * 16);
        const int cur = it & 1;
        const uint32_t* Ac = As[cur];
        const uint32_t* Bc = Bs[cur];

#pragma unroll
        for (int kk = 0; kk < 2; ++kk) {
            uint32_t af[4][4], bf[4][2];
#pragma unroll
            for (int mt = 0; mt < 4; ++mt) {
                int r    = wm * 64 + mt * 16 + (lane >> 2);
                int base = r * 20 + kk * 8 + (lane & 3);
                af[mt][0] = Ac[base];
                af[mt][1] = Ac[base + 160];
                af[mt][2] = Ac[base + 4];
                af[mt][3] = Ac[base + 164];
            }
#pragma unroll
            for (int nt = 0; nt < 4; ++nt) {
                int n    = wn * 32 + nt * 8 + (lane >> 2);
                int base = n * 20 + kk * 8 + (lane & 3);
                bf[nt][0] = Bc[base];
                bf[nt][1] = Bc[base + 4];
            }
#pragma unroll
            for (int mt = 0; mt < 4; ++mt)
#pragma unroll
                for (int nt = 0; nt < 4; ++nt)
                    mma_tf32(acc[mt][nt], af[mt], bf[nt]);
        }

        if (it + 1 < NIT) sts((it + 1) & 1);
        __syncthreads();
    }

#pragma unroll
    for (int mt = 0; mt < 4; ++mt) {
#pragma unroll
        for (int nt = 0; nt < 4; ++nt) {
            int row = m0 + wm * 64 + mt * 16 + (lane >> 2);
            int col = n0 + wn * 32 + nt * 8 + (lane & 3) * 2;
            float b0 = bias[col], b1 = bias[col + 1];
            float* a = acc[mt][nt];
            float2 v0 = { a[0] + b0, a[1] + b1 };
            float2 v1 = { a[2] + b0, a[3] + b1 };
            if (MODE == 1) {
                *(float2*)&Cout[(size_t)row * EMB + col] = v0;
                *(float2*)&Cout[(size_t)(row + 8) * EMB + col] = v1;
            } else {
                int which = col >> 10, e = col & 1023, h = e >> 6, d = e & 63;
                float* dst = (which == 0) ? g_q : (which == 1) ? g_k : g_v;
                int b_ = row >> 11;
                size_t base = (size_t)(b_ * HEADS + h) * SEQ;
                *(float2*)&dst[(base + (row & 2047)) * HDIM + d] = v0;
                *(float2*)&dst[(base + ((row + 8) & 2047)) * HDIM + d] = v1;
            }
        }
    }
}

// ---------------------------------------------------------------------------
// FP16 tensor-core flash attention (k16 HMMA, packed half2 k-pairs).
// grid (SEQ/128, BATCH*HEADS), 256 threads = 8 warps x 16 query rows.
// No cp.async / ldmatrix; conversion at STS time via cvt.rn.f16x2.f32.
// Layouts (uint32 words, each = half2 of adjacent k):
//   Q staging: word[r][kp], stride 36, r=0..127, kp=0..31 (reuses K/V region)
//   Ks: word[n][kp],  stride 36, n=0..63  (2304 words)
//   Vs: word[kp][d],  stride 72, kp=0..31 (2304 words), word = {V[2kp][d], V[2kp+1][d]}
// ---------------------------------------------------------------------------
__global__ __launch_bounds__(256)
void fattn_h()
{
    __shared__ uint32_t smem[4608];          // 18 KB
    uint32_t* Ks = smem;                     // 64*36
    uint32_t* Vs = smem + 2304;              // 32*72

    const int tid = threadIdx.x, lane = tid & 31, wid = tid >> 5;
    const int j = lane & 3;
    const int bh = blockIdx.y, q0 = blockIdx.x * 128;

    const float* Qg = g_q + ((size_t)bh * SEQ + q0) * HDIM;
    const float* Kg = g_k + (size_t)bh * SEQ * HDIM;
    const float* Vg = g_v + (size_t)bh * SEQ * HDIM;

    // ---- stage Q (128 x 64) as packed half2, stride 36; lift frags to regs
#pragma unroll
    for (int l = 0; l < 8; ++l) {
        int id = tid + l * 256;              // 0..2047
        int row = id >> 4, c4 = (id & 15) * 4;
        float4 v = *(const float4*)(Qg + row * HDIM + c4);
        uint2 w = make_uint2(h2pk(v.x, v.y), h2pk(v.z, v.w));
        *(uint2*)&smem[row * 36 + c4 / 2] = w;
    }
    __syncthreads();

    uint32_t qf[4][4];
    {
        int r = wid * 16 + (lane >> 2);
#pragma unroll
        for (int kt = 0; kt < 4; ++kt) {
            int base = r * 36 + kt * 8 + j;
            qf[kt][0] = smem[base];              // (r,   k0..k0+1)
            qf[kt][1] = smem[base + 8 * 36];     // (r+8, k0..k0+1)
            qf[kt][2] = smem[base + 4];          // (r,   k0+8..9)
            qf[kt][3] = smem[base + 8 * 36 + 4]; // (r+8, k0+8..9)
        }
    }
    __syncthreads();

    float oacc[8][4];
#pragma unroll
    for (int i = 0; i < 8; ++i)
#pragma unroll
        for (int r = 0; r < 4; ++r) oacc[i][r] = 0.f;
    float mrun0 = -1e30f, mrun1 = -1e30f;
    float lrun0 = 0.f, lrun1 = 0.f;
    const float C2 = 0.18033688f;            // log2(e) / sqrt(64)

    for (int t = 0; t < SEQ / 64; ++t) {
        const float* Kt = Kg + (size_t)t * 64 * HDIM;
        const float* Vt = Vg + (size_t)t * 64 * HDIM;
        // K: 64 rows x 64 k -> word[n][kp]
#pragma unroll
        for (int l = 0; l < 4; ++l) {
            int id = tid + l * 256;          // 0..1023
            int n = id >> 4, c4 = (id & 15) * 4;
            float4 a = *(const float4*)(Kt + n * HDIM + c4);
            uint2 w = make_uint2(h2pk(a.x, a.y), h2pk(a.z, a.w));
            *(uint2*)&Ks[n * 36 + c4 / 2] = w;
        }
        // V: 32 kp-rows x 64 d -> word[kp][d] = {V[2kp][d], V[2kp+1][d]}
#pragma unroll
        for (int l = 0; l < 2; ++l) {
            int id = tid + l * 256;          // 0..511
            int kp = id >> 4, d4 = (id & 15) * 4;
            float4 v0 = *(const float4*)(Vt + (2 * kp) * HDIM + d4);
            float4 v1 = *(const float4*)(Vt + (2 * kp + 1) * HDIM + d4);
            uint4 w = make_uint4(h2pk(v0.x, v1.x), h2pk(v0.y, v1.y),
                                 h2pk(v0.z, v1.z), h2pk(v0.w, v1.w));
            *(uint4*)&Vs[kp * 72 + d4] = w;
        }
        __syncthreads();

        // ---- S = Q K^T : per warp 16 x 64, 32 k16 mmas
        float sacc[8][4];
#pragma unroll
        for (int i = 0; i < 8; ++i)
#pragma unroll
            for (int r = 0; r < 4; ++r) sacc[i][r] = 0.f;
#pragma unroll
        for (int nt = 0; nt < 8; ++nt) {
            int n = nt * 8 + (lane >> 2);
#pragma unroll
            for (int kt = 0; kt < 4; ++kt) {
                int base = n * 36 + kt * 8 + j;
                uint32_t kf[2] = { Ks[base], Ks[base + 4] };
                mma_f16(sacc[nt], qf[kt], kf);
            }
        }

        // ---- online softmax
        float mx0 = -1e30f, mx1 = -1e30f;
#pragma unroll
        for (int i = 0; i < 8; ++i) {
            mx0 = fmaxf(mx0, fmaxf(sacc[i][0], sacc[i][1]));
            mx1 = fmaxf(mx1, fmaxf(sacc[i][2], sacc[i][3]));
        }
        mx0 = fmaxf(mx0, __shfl_xor_sync(0xffffffffu, mx0, 1));
        mx0 = fmaxf(mx0, __shfl_xor_sync(0xffffffffu, mx0, 2));
        mx1 = fmaxf(mx1, __shfl_xor_sync(0xffffffffu, mx1, 1));
        mx1 = fmaxf(mx1, __shfl_xor_sync(0xffffffffu, mx1, 2));
        float mn0 = fmaxf(mrun0, mx0), mn1 = fmaxf(mrun1, mx1);
        float c0 = ex2f((mrun0 - mn0) * C2), c1 = ex2f((mrun1 - mn1) * C2);
        mrun0 = mn0; mrun1 = mn1;
#pragma unroll
        for (int i = 0; i < 8; ++i) {
            oacc[i][0] *= c0; oacc[i][1] *= c0;
            oacc[i][2] *= c1; oacc[i][3] *= c1;
        }
        lrun0 *= c0; lrun1 *= c1;

        // ---- exp + PV. k16 geometry: thread's D-cols (2j,2j+1) of
        // sacc[2kt],sacc[2kt+1] ARE its A-fragment k-pairs -> no shuffles.
#pragma unroll
        for (int kt = 0; kt < 4; ++kt) {
            float p00 = ex2f((sacc[2*kt  ][0] - mn0) * C2);  // (r,   kt*16+2j)
            float p01 = ex2f((sacc[2*kt  ][1] - mn0) * C2);  // (r,   kt*16+2j+1)
            float p02 = ex2f((sacc[2*kt  ][2] - mn1) * C2);  // (r+8, ...)
            float p03 = ex2f((sacc[2*kt  ][3] - mn1) * C2);
            float p10 = ex2f((sacc[2*kt+1][0] - mn0) * C2);  // (r,   kt*16+8+2j)
            float p11 = ex2f((sacc[2*kt+1][1] - mn0) * C2);
            float p12 = ex2f((sacc[2*kt+1][2] - mn1) * C2);  // (r+8, ...)
            float p13 = ex2f((sacc[2*kt+1][3] - mn1) * C2);
            lrun0 += p00 + p01 + p10 + p11;
            lrun1 += p02 + p03 + p12 + p13;

            uint32_t pa[4];
            pa[0] = h2pk(p00, p01);   // (r,   k0..k0+1)
            pa[1] = h2pk(p02, p03);   // (r+8, k0..k0+1)
            pa[2] = h2pk(p10, p11);   // (r,   k0+8..9)
            pa[3] = h2pk(p12, p13);   // (r+8, k0+8..9)

#pragma unroll
            for (int nt = 0; nt < 8; ++nt) {
                int base = (kt * 8 + j) * 72 + nt * 8 + (lane >> 2);
                uint32_t vf[2] = { Vs[base], Vs[base + 4 * 72] };
                mma_f16(oacc[nt], pa, vf);
            }
        }
        __syncthreads();
    }

    // ---- epilogue: quad-reduce l, normalize, store [b, n, emb]
    lrun0 += __shfl_xor_sync(0xffffffffu, lrun0, 1);
    lrun0 += __shfl_xor_sync(0xffffffffu, lrun0, 2);
    lrun1 += __shfl_xor_sync(0xffffffffu, lrun1, 1);
    lrun1 += __shfl_xor_sync(0xffffffffu, lrun1, 2);
    float inv0 = 1.f / lrun0;
    float inv1 = 1.f / lrun1;

    int b_ = bh >> 4, h = bh & 15;
    int row = q0 + wid * 16 + (lane >> 2);
    size_t base0 = ((size_t)b_ * SEQ + row) * EMB + h * HDIM;
    size_t base1 = base0 + (size_t)8 * EMB;
#pragma unroll
    for (int nt = 0; nt < 8; ++nt) {
        int d = nt * 8 + (lane & 3) * 2;
        *(float2*)&g_att[base0 + d] = make_float2(oacc[nt][0] * inv0, oacc[nt][1] * inv0);
        *(float2*)&g_att[base1 + d] = make_float2(oacc[nt][2] * inv1, oacc[nt][3] * inv1);
    }
}

// ---------------------------------------------------------------------------
extern "C" void kernel_launch(void* const* d_in, const int* in_sizes, int n_in,
                              void* d_out, int out_size)
{
    const float* x      = (const float*)d_in[0];
    const float* w_qkv  = (const float*)d_in[1];
    const float* b_qkv  = (const float*)d_in[2];
    const float* w_proj = (const float*)d_in[3];
    const float* b_proj = (const float*)d_in[4];
    float* out = (float*)d_out;

    tgemm<0><<<dim3(QKVN / 128, MTOT / 128), 256>>>(x, w_qkv, b_qkv, nullptr);    // (24,64)

    fattn_h<<<dim3(SEQ / 128, BATCH * HEADS), 256>>>();                           // (16,64)

    tgemm<1><<<dim3(EMB / 128, MTOT / 128), 256>>>(nullptr, w_proj, b_proj, out); // (8,64)
}

// round 12
// speedup vs baseline: 6.2317x; 1.3074x over previous
#include <cuda_runtime.h>
#include <cstdint>

#define BATCH 4
#define SEQ   2048
#define EMB   1024
#define HEADS 16
#define HDIM  64
#define MTOT  (BATCH*SEQ)      // 8192
#define QKVN  (3*EMB)          // 3072

// Scratch (static device memory — no allocations allowed)
__device__ float g_q[BATCH*HEADS*SEQ*HDIM];   // [b,h,n,d]
__device__ float g_k[BATCH*HEADS*SEQ*HDIM];
__device__ float g_v[BATCH*HEADS*SEQ*HDIM];
__device__ float g_att[MTOT*EMB];             // [b,n,emb]

// ---------------- helpers ----------------------------------------------------
__device__ __forceinline__ float ex2f(float x) {
    float r; asm("ex2.approx.ftz.f32 %0, %1;" : "=f"(r) : "f"(x)); return r;
}
// pack two fp32 -> f16x2 word: low half = lo, high half = hi (first src = high)
__device__ __forceinline__ uint32_t h2pk(float lo, float hi) {
    uint32_t r; asm("cvt.rn.f16x2.f32 %0, %1, %2;" : "=r"(r) : "f"(hi), "f"(lo));
    return r;
}
// fp16 mma, fp32 accumulate
__device__ __forceinline__ void mma_f16(float* c, const uint32_t* a, const uint32_t* b) {
    asm volatile("mma.sync.aligned.m16n8k16.row.col.f32.f16.f16.f32 "
        "{%0,%1,%2,%3}, {%4,%5,%6,%7}, {%8,%9}, {%0,%1,%2,%3};"
        : "+f"(c[0]), "+f"(c[1]), "+f"(c[2]), "+f"(c[3])
        : "r"(a[0]), "r"(a[1]), "r"(a[2]), "r"(a[3]), "r"(b[0]), "r"(b[1]));
}

// ---------------------------------------------------------------------------
// FP16 tensor-core NT GEMM, double-buffered + register-prefetch pipeline:
// C[M,N] = A[M,K] @ B[N,K]^T + bias.  Data plane: packed half2 k-pairs
// (word[row][kp], stride 12 = 8 words + 4 pad; conflict-free LDS gathers).
// MODE 0: A = x, B = w_qkv, epilogue scatters fp32 into g_q/g_k/g_v [b,h,n,d]
// MODE 1: A = g_att, B = w_proj, epilogue writes Cout with bias
// ---------------------------------------------------------------------------
template<int MODE>
__global__ __launch_bounds__(256, 2)
void hgemm(const float* __restrict__ A, const float* __restrict__ Bm,
           const float* __restrict__ bias, float* __restrict__ Cout)
{
    constexpr int K = 1024;
    constexpr int NIT = K / 16;
    __shared__ uint32_t As[2][128 * 12];   // word[m][kp] half2, stride 12
    __shared__ uint32_t Bs[2][128 * 12];   // word[n][kp] half2

    const int tid = threadIdx.x, lane = tid & 31, wid = tid >> 5;
    const int j = lane & 3;
    const int wm = wid & 1, wn = wid >> 1;          // 2 x 4 warp grid
    const int m0 = blockIdx.y * 128, n0 = blockIdx.x * 128;

    const float* Ag = ((MODE == 1) ? (const float*)g_att : A) + (size_t)m0 * K;
    const float* Bg = Bm + (size_t)n0 * K;

    // staging: 512 float4 chunks per tensor per stage; 2 chunks per thread
    const int r0 = tid >> 2,  c0 = (tid & 3) * 4;   // floats
    const int r1 = r0 + 64,   c1 = c0;

    float4 pva[2], pvb[2];
    auto ldg = [&](int k0) {
        pva[0] = *(const float4*)(Ag + (size_t)r0 * K + k0 + c0);
        pvb[0] = *(const float4*)(Bg + (size_t)r0 * K + k0 + c0);
        pva[1] = *(const float4*)(Ag + (size_t)r1 * K + k0 + c1);
        pvb[1] = *(const float4*)(Bg + (size_t)r1 * K + k0 + c1);
    };
    auto sts = [&](int st) {
        *(uint2*)&As[st][r0 * 12 + c0 / 2] =
            make_uint2(h2pk(pva[0].x, pva[0].y), h2pk(pva[0].z, pva[0].w));
        *(uint2*)&Bs[st][r0 * 12 + c0 / 2] =
            make_uint2(h2pk(pvb[0].x, pvb[0].y), h2pk(pvb[0].z, pvb[0].w));
        *(uint2*)&As[st][r1 * 12 + c1 / 2] =
            make_uint2(h2pk(pva[1].x, pva[1].y), h2pk(pva[1].z, pva[1].w));
        *(uint2*)&Bs[st][r1 * 12 + c1 / 2] =
            make_uint2(h2pk(pvb[1].x, pvb[1].y), h2pk(pvb[1].z, pvb[1].w));
    };

    float acc[4][4][4];
#pragma unroll
    for (int i = 0; i < 4; ++i)
#pragma unroll
        for (int jj = 0; jj < 4; ++jj)
#pragma unroll
            for (int r = 0; r < 4; ++r) acc[i][jj][r] = 0.f;

    ldg(0); sts(0);
    __syncthreads();

    for (int it = 0; it < NIT; ++it) {
        if (it + 1 < NIT) ldg((it + 1) * 16);       // overlaps mma below
        const int cur = it & 1;
        const uint32_t* Ac = As[cur];
        const uint32_t* Bc = Bs[cur];

        uint32_t af[4][4], bf[4][2];
#pragma unroll
        for (int mt = 0; mt < 4; ++mt) {
            int r    = wm * 64 + mt * 16 + (lane >> 2);
            int base = r * 12 + j;
            af[mt][0] = Ac[base];           // (r,   k 2j..2j+1)
            af[mt][1] = Ac[base + 96];      // (r+8, k 2j..2j+1)
            af[mt][2] = Ac[base + 4];       // (r,   k 2j+8..9)
            af[mt][3] = Ac[base + 100];     // (r+8, k 2j+8..9)
        }
#pragma unroll
        for (int nt = 0; nt < 4; ++nt) {
            int n    = wn * 32 + nt * 8 + (lane >> 2);
            int base = n * 12 + j;
            bf[nt][0] = Bc[base];           // (k 2j..2j+1,  n)
            bf[nt][1] = Bc[base + 4];       // (k 2j+8..9,   n)
        }
#pragma unroll
        for (int mt = 0; mt < 4; ++mt)
#pragma unroll
            for (int nt = 0; nt < 4; ++nt)
                mma_f16(acc[mt][nt], af[mt], bf[nt]);

        if (it + 1 < NIT) sts((it + 1) & 1);
        __syncthreads();
    }

#pragma unroll
    for (int mt = 0; mt < 4; ++mt) {
#pragma unroll
        for (int nt = 0; nt < 4; ++nt) {
            int row = m0 + wm * 64 + mt * 16 + (lane >> 2);
            int col = n0 + wn * 32 + nt * 8 + j * 2;
            float b0 = bias[col], b1 = bias[col + 1];
            float* a = acc[mt][nt];
            float2 v0 = { a[0] + b0, a[1] + b1 };
            float2 v1 = { a[2] + b0, a[3] + b1 };
            if (MODE == 1) {
                *(float2*)&Cout[(size_t)row * EMB + col] = v0;
                *(float2*)&Cout[(size_t)(row + 8) * EMB + col] = v1;
            } else {
                int which = col >> 10, e = col & 1023, h = e >> 6, d = e & 63;
                float* dst = (which == 0) ? g_q : (which == 1) ? g_k : g_v;
                int b_ = row >> 11;
                size_t base = (size_t)(b_ * HEADS + h) * SEQ;
                *(float2*)&dst[(base + (row & 2047)) * HDIM + d] = v0;
                *(float2*)&dst[(base + ((row + 8) & 2047)) * HDIM + d] = v1;
            }
        }
    }
}

// ---------------------------------------------------------------------------
// FP16 tensor-core flash attention (round-11 PASSING version, unchanged).
// grid (SEQ/128, BATCH*HEADS), 256 threads = 8 warps x 16 query rows.
// ---------------------------------------------------------------------------
__global__ __launch_bounds__(256)
void fattn_h()
{
    __shared__ uint32_t smem[4608];          // 18 KB
    uint32_t* Ks = smem;                     // 64*36
    uint32_t* Vs = smem + 2304;              // 32*72

    const int tid = threadIdx.x, lane = tid & 31, wid = tid >> 5;
    const int j = lane & 3;
    const int bh = blockIdx.y, q0 = blockIdx.x * 128;

    const float* Qg = g_q + ((size_t)bh * SEQ + q0) * HDIM;
    const float* Kg = g_k + (size_t)bh * SEQ * HDIM;
    const float* Vg = g_v + (size_t)bh * SEQ * HDIM;

    // ---- stage Q (128 x 64) as packed half2, stride 36; lift frags to regs
#pragma unroll
    for (int l = 0; l < 8; ++l) {
        int id = tid + l * 256;              // 0..2047
        int row = id >> 4, c4 = (id & 15) * 4;
        float4 v = *(const float4*)(Qg + row * HDIM + c4);
        uint2 w = make_uint2(h2pk(v.x, v.y), h2pk(v.z, v.w));
        *(uint2*)&smem[row * 36 + c4 / 2] = w;
    }
    __syncthreads();

    uint32_t qf[4][4];
    {
        int r = wid * 16 + (lane >> 2);
#pragma unroll
        for (int kt = 0; kt < 4; ++kt) {
            int base = r * 36 + kt * 8 + j;
            qf[kt][0] = smem[base];              // (r,   k0..k0+1)
            qf[kt][1] = smem[base + 8 * 36];     // (r+8, k0..k0+1)
            qf[kt][2] = smem[base + 4];          // (r,   k0+8..9)
            qf[kt][3] = smem[base + 8 * 36 + 4]; // (r+8, k0+8..9)
        }
    }
    __syncthreads();

    float oacc[8][4];
#pragma unroll
    for (int i = 0; i < 8; ++i)
#pragma unroll
        for (int r = 0; r < 4; ++r) oacc[i][r] = 0.f;
    float mrun0 = -1e30f, mrun1 = -1e30f;
    float lrun0 = 0.f, lrun1 = 0.f;
    const float C2 = 0.18033688f;            // log2(e) / sqrt(64)

    for (int t = 0; t < SEQ / 64; ++t) {
        const float* Kt = Kg + (size_t)t * 64 * HDIM;
        const float* Vt = Vg + (size_t)t * 64 * HDIM;
        // K: 64 rows x 64 k -> word[n][kp]
#pragma unroll
        for (int l = 0; l < 4; ++l) {
            int id = tid + l * 256;          // 0..1023
            int n = id >> 4, c4 = (id & 15) * 4;
            float4 a = *(const float4*)(Kt + n * HDIM + c4);
            uint2 w = make_uint2(h2pk(a.x, a.y), h2pk(a.z, a.w));
            *(uint2*)&Ks[n * 36 + c4 / 2] = w;
        }
        // V: 32 kp-rows x 64 d -> word[kp][d] = {V[2kp][d], V[2kp+1][d]}
#pragma unroll
        for (int l = 0; l < 2; ++l) {
            int id = tid + l * 256;          // 0..511
            int kp = id >> 4, d4 = (id & 15) * 4;
            float4 v0 = *(const float4*)(Vt + (2 * kp) * HDIM + d4);
            float4 v1 = *(const float4*)(Vt + (2 * kp + 1) * HDIM + d4);
            uint4 w = make_uint4(h2pk(v0.x, v1.x), h2pk(v0.y, v1.y),
                                 h2pk(v0.z, v1.z), h2pk(v0.w, v1.w));
            *(uint4*)&Vs[kp * 72 + d4] = w;
        }
        __syncthreads();

        // ---- S = Q K^T : per warp 16 x 64, 32 k16 mmas
        float sacc[8][4];
#pragma unroll
        for (int i = 0; i < 8; ++i)
#pragma unroll
            for (int r = 0; r < 4; ++r) sacc[i][r] = 0.f;
#pragma unroll
        for (int nt = 0; nt < 8; ++nt) {
            int n = nt * 8 + (lane >> 2);
#pragma unroll
            for (int kt = 0; kt < 4; ++kt) {
                int base = n * 36 + kt * 8 + j;
                uint32_t kf[2] = { Ks[base], Ks[base + 4] };
                mma_f16(sacc[nt], qf[kt], kf);
            }
        }

        // ---- online softmax
        float mx0 = -1e30f, mx1 = -1e30f;
#pragma unroll
        for (int i = 0; i < 8; ++i) {
            mx0 = fmaxf(mx0, fmaxf(sacc[i][0], sacc[i][1]));
            mx1 = fmaxf(mx1, fmaxf(sacc[i][2], sacc[i][3]));
        }
        mx0 = fmaxf(mx0, __shfl_xor_sync(0xffffffffu, mx0, 1));
        mx0 = fmaxf(mx0, __shfl_xor_sync(0xffffffffu, mx0, 2));
        mx1 = fmaxf(mx1, __shfl_xor_sync(0xffffffffu, mx1, 1));
        mx1 = fmaxf(mx1, __shfl_xor_sync(0xffffffffu, mx1, 2));
        float mn0 = fmaxf(mrun0, mx0), mn1 = fmaxf(mrun1, mx1);
        float c0 = ex2f((mrun0 - mn0) * C2), c1 = ex2f((mrun1 - mn1) * C2);
        mrun0 = mn0; mrun1 = mn1;
#pragma unroll
        for (int i = 0; i < 8; ++i) {
            oacc[i][0] *= c0; oacc[i][1] *= c0;
            oacc[i][2] *= c1; oacc[i][3] *= c1;
        }
        lrun0 *= c0; lrun1 *= c1;

        // ---- exp + PV. k16 geometry: thread's D-cols (2j,2j+1) of
        // sacc[2kt],sacc[2kt+1] ARE its A-fragment k-pairs -> no shuffles.
#pragma unroll
        for (int kt = 0; kt < 4; ++kt) {
            float p00 = ex2f((sacc[2*kt  ][0] - mn0) * C2);
            float p01 = ex2f((sacc[2*kt  ][1] - mn0) * C2);
            float p02 = ex2f((sacc[2*kt  ][2] - mn1) * C2);
            float p03 = ex2f((sacc[2*kt  ][3] - mn1) * C2);
            float p10 = ex2f((sacc[2*kt+1][0] - mn0) * C2);
            float p11 = ex2f((sacc[2*kt+1][1] - mn0) * C2);
            float p12 = ex2f((sacc[2*kt+1][2] - mn1) * C2);
            float p13 = ex2f((sacc[2*kt+1][3] - mn1) * C2);
            lrun0 += p00 + p01 + p10 + p11;
            lrun1 += p02 + p03 + p12 + p13;

            uint32_t pa[4];
            pa[0] = h2pk(p00, p01);
            pa[1] = h2pk(p02, p03);
            pa[2] = h2pk(p10, p11);
            pa[3] = h2pk(p12, p13);

#pragma unroll
            for (int nt = 0; nt < 8; ++nt) {
                int base = (kt * 8 + j) * 72 + nt * 8 + (lane >> 2);
                uint32_t vf[2] = { Vs[base], Vs[base + 4 * 72] };
                mma_f16(oacc[nt], pa, vf);
            }
        }
        __syncthreads();
    }

    // ---- epilogue: quad-reduce l, normalize, store [b, n, emb]
    lrun0 += __shfl_xor_sync(0xffffffffu, lrun0, 1);
    lrun0 += __shfl_xor_sync(0xffffffffu, lrun0, 2);
    lrun1 += __shfl_xor_sync(0xffffffffu, lrun1, 1);
    lrun1 += __shfl_xor_sync(0xffffffffu, lrun1, 2);
    float inv0 = 1.f / lrun0;
    float inv1 = 1.f / lrun1;

    int b_ = bh >> 4, h = bh & 15;
    int row = q0 + wid * 16 + (lane >> 2);
    size_t base0 = ((size_t)b_ * SEQ + row) * EMB + h * HDIM;
    size_t base1 = base0 + (size_t)8 * EMB;
#pragma unroll
    for (int nt = 0; nt < 8; ++nt) {
        int d = nt * 8 + j * 2;
        *(float2*)&g_att[base0 + d] = make_float2(oacc[nt][0] * inv0, oacc[nt][1] * inv0);
        *(float2*)&g_att[base1 + d] = make_float2(oacc[nt][2] * inv1, oacc[nt][3] * inv1);
    }
}

// ---------------------------------------------------------------------------
extern "C" void kernel_launch(void* const* d_in, const int* in_sizes, int n_in,
                              void* d_out, int out_size)
{
    const float* x      = (const float*)d_in[0];
    const float* w_qkv  = (const float*)d_in[1];
    const float* b_qkv  = (const float*)d_in[2];
    const float* w_proj = (const float*)d_in[3];
    const float* b_proj = (const float*)d_in[4];
    float* out = (float*)d_out;

    hgemm<0><<<dim3(QKVN / 128, MTOT / 128), 256>>>(x, w_qkv, b_qkv, nullptr);    // (24,64)

    fattn_h<<<dim3(SEQ / 128, BATCH * HEADS), 256>>>();                           // (16,64)

    hgemm<1><<<dim3(EMB / 128, MTOT / 128), 256>>>(nullptr, w_proj, b_proj, out); // (8,64)
}

// round 14
// speedup vs baseline: 6.4669x; 1.0377x over previous
#include <cuda_runtime.h>
#include <cstdint>

#define BATCH 4
#define SEQ   2048
#define EMB   1024
#define HEADS 16
#define HDIM  64
#define MTOT  (BATCH*SEQ)      // 8192
#define QKVN  (3*EMB)          // 3072

// Scratch (static device memory — no allocations allowed).
// All fp16 tensors stored as uint32 words = packed half2 (low = even idx).
__device__ uint32_t g_xh[MTOT*EMB/2];        // x fp16
__device__ uint32_t g_wqkvh[QKVN*EMB/2];     // w_qkv fp16
__device__ uint32_t g_wprojh[EMB*EMB/2];     // w_proj fp16
__device__ uint32_t g_qh[BATCH*HEADS*SEQ*HDIM/2];   // [b,h,n,d] fp16
__device__ uint32_t g_kh[BATCH*HEADS*SEQ*HDIM/2];
__device__ uint32_t g_vh[BATCH*HEADS*SEQ*HDIM/2];
__device__ uint32_t g_atth[MTOT*EMB/2];      // [b,n,emb] fp16

// ---------------- helpers ----------------------------------------------------
__device__ __forceinline__ float ex2f(float x) {
    float r; asm("ex2.approx.ftz.f32 %0, %1;" : "=f"(r) : "f"(x)); return r;
}
// pack two fp32 -> f16x2 word: low half = lo, high half = hi (first src = high)
__device__ __forceinline__ uint32_t h2pk(float lo, float hi) {
    uint32_t r; asm("cvt.rn.f16x2.f32 %0, %1, %2;" : "=r"(r) : "f"(hi), "f"(lo));
    return r;
}
// fp16 mma, fp32 accumulate
__device__ __forceinline__ void mma_f16(float* c, const uint32_t* a, const uint32_t* b) {
    asm volatile("mma.sync.aligned.m16n8k16.row.col.f32.f16.f16.f32 "
        "{%0,%1,%2,%3}, {%4,%5,%6,%7}, {%8,%9}, {%0,%1,%2,%3};"
        : "+f"(c[0]), "+f"(c[1]), "+f"(c[2]), "+f"(c[3])
        : "r"(a[0]), "r"(a[1]), "r"(a[2]), "r"(a[3]), "r"(b[0]), "r"(b[1]));
}

// ---------------- fp32 -> fp16 convert kernels -------------------------------
// T: 0 -> g_xh, 1 -> g_wqkvh, 2 -> g_wprojh
template<int T>
__global__ void f2h(const float4* __restrict__ s, int n4)
{
    uint32_t* dst = (T == 0) ? g_xh : (T == 1) ? g_wqkvh : g_wprojh;
    int i = blockIdx.x * blockDim.x + threadIdx.x;
    if (i < n4) {
        float4 v = s[i];
        *(uint2*)&dst[i * 2] = make_uint2(h2pk(v.x, v.y), h2pk(v.z, v.w));
    }
}

// ---------------------------------------------------------------------------
// FP16 tensor-core NT GEMM (fp16 inputs), double-buffered + register
// prefetch.  C[M,N] = A[M,K] @ B[N,K]^T + bias.
// smem: word[row][kp], stride 12 (8 words + 4 pad), conflict-free gathers.
// MODE 0: A = g_xh, B = g_wqkvh, epilogue -> g_qh/g_kh/g_vh (half words)
// MODE 1: A = g_atth, B = g_wprojh, epilogue -> Cout fp32 with bias
// ---------------------------------------------------------------------------
template<int MODE>
__global__ __launch_bounds__(256, 2)
void hgemm(const float* __restrict__ bias, float* __restrict__ Cout)
{
    constexpr int KW = 512;                // K in words (1024 halves)
    constexpr int NIT = 64;                // 16-k (8-word) tiles
    __shared__ uint32_t As[2][128 * 12];
    __shared__ uint32_t Bs[2][128 * 12];

    const uint32_t* Aw = (MODE == 0) ? g_xh : g_atth;
    const uint32_t* Bw = (MODE == 0) ? g_wqkvh : g_wprojh;

    const int tid = threadIdx.x, lane = tid & 31, wid = tid >> 5;
    const int j = lane & 3;
    const int wm = wid & 1, wn = wid >> 1;          // 2 x 4 warp grid
    const int m0 = blockIdx.y * 128, n0 = blockIdx.x * 128;

    const uint32_t* Ag = Aw + (size_t)m0 * KW;
    const uint32_t* Bg = Bw + (size_t)n0 * KW;

    // staging: 256 uint4 chunks per tensor per stage; 1 chunk each per thread
    const int sr = tid >> 1;               // row 0..127
    const int sc = (tid & 1) * 4;          // word offset 0 or 4

    uint4 pva, pvb;                        // prefetch registers (8 regs)
    auto ldg = [&](int k0w) {
        pva = *(const uint4*)(Ag + (size_t)sr * KW + k0w + sc);
        pvb = *(const uint4*)(Bg + (size_t)sr * KW + k0w + sc);
    };
    auto sts = [&](int st) {
        *(uint4*)&As[st][sr * 12 + sc] = pva;
        *(uint4*)&Bs[st][sr * 12 + sc] = pvb;
    };

    float acc[4][4][4];
#pragma unroll
    for (int i = 0; i < 4; ++i)
#pragma unroll
        for (int jj = 0; jj < 4; ++jj)
#pragma unroll
            for (int r = 0; r < 4; ++r) acc[i][jj][r] = 0.f;

    ldg(0); sts(0);
    __syncthreads();

    for (int it = 0; it < NIT; ++it) {
        if (it + 1 < NIT) ldg((it + 1) * 8);        // overlaps mma below
        const int cur = it & 1;
        const uint32_t* Ac = As[cur];
        const uint32_t* Bc = Bs[cur];

        uint32_t af[4][4], bf[4][2];
#pragma unroll
        for (int mt = 0; mt < 4; ++mt) {
            int r    = wm * 64 + mt * 16 + (lane >> 2);
            int base = r * 12 + j;
            af[mt][0] = Ac[base];           // (r,   k 2j..2j+1)
            af[mt][1] = Ac[base + 96];      // (r+8, k 2j..2j+1)
            af[mt][2] = Ac[base + 4];       // (r,   k 2j+8..9)
            af[mt][3] = Ac[base + 100];     // (r+8, k 2j+8..9)
        }
#pragma unroll
        for (int nt = 0; nt < 4; ++nt) {
            int n    = wn * 32 + nt * 8 + (lane >> 2);
            int base = n * 12 + j;
            bf[nt][0] = Bc[base];
            bf[nt][1] = Bc[base + 4];
        }
#pragma unroll
        for (int mt = 0; mt < 4; ++mt)
#pragma unroll
            for (int nt = 0; nt < 4; ++nt)
                mma_f16(acc[mt][nt], af[mt], bf[nt]);

        if (it + 1 < NIT) sts((it + 1) & 1);
        __syncthreads();
    }

#pragma unroll
    for (int mt = 0; mt < 4; ++mt) {
#pragma unroll
        for (int nt = 0; nt < 4; ++nt) {
            int row = m0 + wm * 64 + mt * 16 + (lane >> 2);
            int col = n0 + wn * 32 + nt * 8 + j * 2;
            float b0 = bias[col], b1 = bias[col + 1];
            float* a = acc[mt][nt];
            if (MODE == 1) {
                float2 v0 = { a[0] + b0, a[1] + b1 };
                float2 v1 = { a[2] + b0, a[3] + b1 };
                *(float2*)&Cout[(size_t)row * EMB + col] = v0;
                *(float2*)&Cout[(size_t)(row + 8) * EMB + col] = v1;
            } else {
                uint32_t w0 = h2pk(a[0] + b0, a[1] + b1);
                uint32_t w1 = h2pk(a[2] + b0, a[3] + b1);
                int which = col >> 10, e = col & 1023, h = e >> 6, d = e & 63;
                uint32_t* dst = (which == 0) ? g_qh : (which == 1) ? g_kh : g_vh;
                int b_ = row >> 11;
                size_t base = (size_t)(b_ * HEADS + h) * SEQ;
                dst[(base + (row & 2047)) * 32 + d / 2] = w0;
                dst[(base + ((row + 8) & 2047)) * 32 + d / 2] = w1;
            }
        }
    }
}

// ---------------------------------------------------------------------------
// FP16 tensor-core flash attention (round-12 structure; fp16 gmem in/out).
// grid (SEQ/128, BATCH*HEADS), 256 threads = 8 warps x 16 query rows.
//   Q staging: word[r][kp], stride 36   (pure copy from g_qh)
//   Ks: word[n][kp],  stride 36         (pure copy from g_kh)
//   Vs: word[kp][d],  stride 72, word = {V[2kp][d], V[2kp+1][d]} via byte_perm
// ---------------------------------------------------------------------------
__global__ __launch_bounds__(256)
void fattn_h()
{
    __shared__ uint32_t smem[4608];          // 18 KB
    uint32_t* Ks = smem;                     // 64*36
    uint32_t* Vs = smem + 2304;              // 32*72

    const int tid = threadIdx.x, lane = tid & 31, wid = tid >> 5;
    const int j = lane & 3;
    const int bh = blockIdx.y, q0 = blockIdx.x * 128;

    const uint32_t* Qg = g_qh + ((size_t)bh * SEQ + q0) * 32;   // 32 words/row
    const uint32_t* Kg = g_kh + (size_t)bh * SEQ * 32;
    const uint32_t* Vg = g_vh + (size_t)bh * SEQ * 32;

    // ---- stage Q (128 rows x 32 words), stride 36; lift frags to regs
#pragma unroll
    for (int l = 0; l < 4; ++l) {
        int id = tid + l * 256;              // 0..1023 (uint4 chunks)
        int row = id >> 3, cw = (id & 7) * 4;
        *(uint4*)&smem[row * 36 + cw] = *(const uint4*)(Qg + row * 32 + cw);
    }
    __syncthreads();

    uint32_t qf[4][4];
    {
        int r = wid * 16 + (lane >> 2);
#pragma unroll
        for (int kt = 0; kt < 4; ++kt) {
            int base = r * 36 + kt * 8 + j;
            qf[kt][0] = smem[base];              // (r,   k0..k0+1)
            qf[kt][1] = smem[base + 8 * 36];     // (r+8, k0..k0+1)
            qf[kt][2] = smem[base + 4];          // (r,   k0+8..9)
            qf[kt][3] = smem[base + 8 * 36 + 4]; // (r+8, k0+8..9)
        }
    }
    __syncthreads();

    float oacc[8][4];
#pragma unroll
    for (int i = 0; i < 8; ++i)
#pragma unroll
        for (int r = 0; r < 4; ++r) oacc[i][r] = 0.f;
    float mrun0 = -1e30f, mrun1 = -1e30f;
    float lrun0 = 0.f, lrun1 = 0.f;
    const float C2 = 0.18033688f;            // log2(e) / sqrt(64)

    for (int t = 0; t < SEQ / 64; ++t) {
        const uint32_t* Kt = Kg + (size_t)t * 64 * 32;
        const uint32_t* Vt = Vg + (size_t)t * 64 * 32;
        // K: 64 rows x 32 words -> word[n][kp] (pure copy)
#pragma unroll
        for (int l = 0; l < 2; ++l) {
            int id = tid + l * 256;          // 0..511 (uint4 chunks)
            int n = id >> 3, cw = (id & 7) * 4;
            *(uint4*)&Ks[n * 36 + cw] = *(const uint4*)(Kt + n * 32 + cw);
        }
        // V: interleave rows (2kp, 2kp+1) at each d via byte_perm
#pragma unroll
        for (int l = 0; l < 2; ++l) {
            int id = tid + l * 256;          // 0..511
            int kp = id >> 4, d4 = (id & 15) * 4;    // 4 d-values per chunk
            uint2 r0 = *(const uint2*)(Vt + (2 * kp) * 32 + d4 / 2);
            uint2 r1 = *(const uint2*)(Vt + (2 * kp + 1) * 32 + d4 / 2);
            uint4 w = make_uint4(__byte_perm(r0.x, r1.x, 0x5410),
                                 __byte_perm(r0.x, r1.x, 0x7632),
                                 __byte_perm(r0.y, r1.y, 0x5410),
                                 __byte_perm(r0.y, r1.y, 0x7632));
            *(uint4*)&Vs[kp * 72 + d4] = w;
        }
        __syncthreads();

        // ---- S = Q K^T : per warp 16 x 64, 32 k16 mmas
        float sacc[8][4];
#pragma unroll
        for (int i = 0; i < 8; ++i)
#pragma unroll
            for (int r = 0; r < 4; ++r) sacc[i][r] = 0.f;
#pragma unroll
        for (int nt = 0; nt < 8; ++nt) {
            int n = nt * 8 + (lane >> 2);
#pragma unroll
            for (int kt = 0; kt < 4; ++kt) {
                int base = n * 36 + kt * 8 + j;
                uint32_t kf[2] = { Ks[base], Ks[base + 4] };
                mma_f16(sacc[nt], qf[kt], kf);
            }
        }

        // ---- online softmax
        float mx0 = -1e30f, mx1 = -1e30f;
#pragma unroll
        for (int i = 0; i < 8; ++i) {
            mx0 = fmaxf(mx0, fmaxf(sacc[i][0], sacc[i][1]));
            mx1 = fmaxf(mx1, fmaxf(sacc[i][2], sacc[i][3]));
        }
        mx0 = fmaxf(mx0, __shfl_xor_sync(0xffffffffu, mx0, 1));
        mx0 = fmaxf(mx0, __shfl_xor_sync(0xffffffffu, mx0, 2));
        mx1 = fmaxf(mx1, __shfl_xor_sync(0xffffffffu, mx1, 1));
        mx1 = fmaxf(mx1, __shfl_xor_sync(0xffffffffu, mx1, 2));
        float mn0 = fmaxf(mrun0, mx0), mn1 = fmaxf(mrun1, mx1);
        float c0 = ex2f((mrun0 - mn0) * C2), c1 = ex2f((mrun1 - mn1) * C2);
        mrun0 = mn0; mrun1 = mn1;
#pragma unroll
        for (int i = 0; i < 8; ++i) {
            oacc[i][0] *= c0; oacc[i][1] *= c0;
            oacc[i][2] *= c1; oacc[i][3] *= c1;
        }
        lrun0 *= c0; lrun1 *= c1;

        // ---- exp + PV (k16 geometry: D-cols ARE A k-pairs -> no shuffles)
#pragma unroll
        for (int kt = 0; kt < 4; ++kt) {
            float p00 = ex2f((sacc[2*kt  ][0] - mn0) * C2);
            float p01 = ex2f((sacc[2*kt  ][1] - mn0) * C2);
            float p02 = ex2f((sacc[2*kt  ][2] - mn1) * C2);
            float p03 = ex2f((sacc[2*kt  ][3] - mn1) * C2);
            float p10 = ex2f((sacc[2*kt+1][0] - mn0) * C2);
            float p11 = ex2f((sacc[2*kt+1][1] - mn0) * C2);
            float p12 = ex2f((sacc[2*kt+1][2] - mn1) * C2);
            float p13 = ex2f((sacc[2*kt+1][3] - mn1) * C2);
            lrun0 += p00 + p01 + p10 + p11;
            lrun1 += p02 + p03 + p12 + p13;

            uint32_t pa[4];
            pa[0] = h2pk(p00, p01);
            pa[1] = h2pk(p02, p03);
            pa[2] = h2pk(p10, p11);
            pa[3] = h2pk(p12, p13);

#pragma unroll
            for (int nt = 0; nt < 8; ++nt) {
                int base = (kt * 8 + j) * 72 + nt * 8 + (lane >> 2);
                uint32_t vf[2] = { Vs[base], Vs[base + 4 * 72] };
                mma_f16(oacc[nt], pa, vf);
            }
        }
        __syncthreads();
    }

    // ---- epilogue: quad-reduce l, normalize, store half words [b, n, emb]
    lrun0 += __shfl_xor_sync(0xffffffffu, lrun0, 1);
    lrun0 += __shfl_xor_sync(0xffffffffu, lrun0, 2);
    lrun1 += __shfl_xor_sync(0xffffffffu, lrun1, 1);
    lrun1 += __shfl_xor_sync(0xffffffffu, lrun1, 2);
    float inv0 = 1.f / lrun0;
    float inv1 = 1.f / lrun1;

    int b_ = bh >> 4, h = bh & 15;
    int row = q0 + wid * 16 + (lane >> 2);
    size_t base0w = (((size_t)b_ * SEQ + row) * EMB + h * HDIM) / 2;
    size_t base1w = base0w + (size_t)4 * EMB;     // +8 rows in words
#pragma unroll
    for (int nt = 0; nt < 8; ++nt) {
        int dw = nt * 4 + j;
        g_atth[base0w + dw] = h2pk(oacc[nt][0] * inv0, oacc[nt][1] * inv0);
        g_atth[base1w + dw] = h2pk(oacc[nt][2] * inv1, oacc[nt][3] * inv1);
    }
}

// ---------------------------------------------------------------------------
extern "C" void kernel_launch(void* const* d_in, const int* in_sizes, int n_in,
                              void* d_out, int out_size)
{
    const float* x      = (const float*)d_in[0];
    const float* w_qkv  = (const float*)d_in[1];
    const float* b_qkv  = (const float*)d_in[2];
    const float* w_proj = (const float*)d_in[3];
    const float* b_proj = (const float*)d_in[4];
    float* out = (float*)d_out;

    { int n4 = MTOT * EMB / 4;  f2h<0><<<(n4 + 255) / 256, 256>>>((const float4*)x, n4); }
    { int n4 = QKVN * EMB / 4;  f2h<1><<<(n4 + 255) / 256, 256>>>((const float4*)w_qkv, n4); }
    { int n4 = EMB * EMB / 4;   f2h<2><<<(n4 + 255) / 256, 256>>>((const float4*)w_proj, n4); }

    hgemm<0><<<dim3(QKVN / 128, MTOT / 128), 256>>>(b_qkv, nullptr);    // (24,64)

    fattn_h<<<dim3(SEQ / 128, BATCH * HEADS), 256>>>();                 // (16,64)

    hgemm<1><<<dim3(EMB / 128, MTOT / 128), 256>>>(b_proj, out);        // (8,64)
}

// round 17
// speedup vs baseline: 7.4781x; 1.1564x over previous
#include <cuda_runtime.h>
#include <cstdint>

#define BATCH 4
#define SEQ   2048
#define EMB   1024
#define HEADS 16
#define HDIM  64
#define MTOT  (BATCH*SEQ)      // 8192
#define QKVN  (3*EMB)          // 3072

// Scratch (static device memory — no allocations allowed).
// fp16 tensors as uint32 words = packed half2 (low = even k).
// g_xh / g_wqkvh / g_wprojh / g_atth are PAIR-INTERLEAVED in k: within each
// 8-word group, original word i is stored at position 2*(i&3) + (i>>2), so
// the (k, k+8) halves pair needed by a k16 mma fragment is one uint2.
__device__ uint32_t g_xh[MTOT*EMB/2];
__device__ uint32_t g_wqkvh[QKVN*EMB/2];
__device__ uint32_t g_wprojh[EMB*EMB/2];
__device__ uint32_t g_qh[BATCH*HEADS*SEQ*HDIM/2];   // [b,h,n,d] natural
__device__ uint32_t g_kh[BATCH*HEADS*SEQ*HDIM/2];   // natural
__device__ uint32_t g_vh[BATCH*HEADS*SEQ*HDIM/2];   // natural
__device__ uint32_t g_atth[MTOT*EMB/2];             // [b,n,emb] interleaved

// ---------------- helpers ----------------------------------------------------
__device__ __forceinline__ float ex2f(float x) {
    float r; asm("ex2.approx.ftz.f32 %0, %1;" : "=f"(r) : "f"(x)); return r;
}
__device__ __forceinline__ uint32_t h2pk(float lo, float hi) {
    uint32_t r; asm("cvt.rn.f16x2.f32 %0, %1, %2;" : "=r"(r) : "f"(hi), "f"(lo));
    return r;
}
__device__ __forceinline__ void mma_f16(float* c, const uint32_t* a, const uint32_t* b) {
    asm volatile("mma.sync.aligned.m16n8k16.row.col.f32.f16.f16.f32 "
        "{%0,%1,%2,%3}, {%4,%5,%6,%7}, {%8,%9}, {%0,%1,%2,%3};"
        : "+f"(c[0]), "+f"(c[1]), "+f"(c[2]), "+f"(c[3])
        : "r"(a[0]), "r"(a[1]), "r"(a[2]), "r"(a[3]), "r"(b[0]), "r"(b[1]));
}

// ---------------- fp32 -> fp16 convert (emits pair-interleaved words) --------
// T: 0 -> g_xh, 1 -> g_wqkvh, 2 -> g_wprojh
template<int T>
__global__ void f2h(const float4* __restrict__ s, int n4)
{
    uint32_t* dst = (T == 0) ? g_xh : (T == 1) ? g_wqkvh : g_wprojh;
    int i = blockIdx.x * blockDim.x + threadIdx.x;
    if (i < n4) {
        float4 v = s[i];
        uint32_t w0 = h2pk(v.x, v.y);       // original word 2i (even)
        uint32_t w1 = h2pk(v.z, v.w);       // original word 2i+1 (odd)
        int base = (2 * i) & ~7;            // 8-word group start
        int i0 = (2 * i) & 7, i1 = i0 + 1;
        dst[base + ((i0 & 3) << 1) + (i0 >> 2)] = w0;
        dst[base + ((i1 & 3) << 1) + (i1 >> 2)] = w1;
    }
}

// ---------------------------------------------------------------------------
// FP16 tensor-core NT GEMM, BK=32, pair-interleaved k layout -> all fragment
// gathers are LDS.64.  Double-buffered smem + register prefetch.
// smem: word[row][p], stride 24 (16 words + 8 pad; LDS.64 conflict-free).
// MODE 0: A = g_xh, B = g_wqkvh, epilogue -> g_qh/g_kh/g_vh (natural words)
// MODE 1: A = g_atth, B = g_wprojh, epilogue -> Cout fp32 with bias
// ---------------------------------------------------------------------------
template<int MODE>
__global__ __launch_bounds__(256, 2)
void hgemm(const float* __restrict__ bias, float* __restrict__ Cout)
{
    constexpr int KW = 512;                // K in words
    constexpr int NIT = 32;                // 32-k (16-word) tiles
    __shared__ uint32_t As[2][128 * 24];   // 12 KB per stage
    __shared__ uint32_t Bs[2][128 * 24];

    const uint32_t* Aw = (MODE == 0) ? g_xh : g_atth;
    const uint32_t* Bw = (MODE == 0) ? g_wqkvh : g_wprojh;

    const int tid = threadIdx.x, lane = tid & 31, wid = tid >> 5;
    const int j = lane & 3;
    const int wm = wid & 1, wn = wid >> 1;          // 2 x 4 warp grid
    const int m0 = blockIdx.y * 128, n0 = blockIdx.x * 128;

    const uint32_t* Ag = Aw + (size_t)m0 * KW;
    const uint32_t* Bg = Bw + (size_t)n0 * KW;

    // staging: 512 uint4 chunks per tensor per stage; 2 chunks per thread
    const int sr = tid >> 2;               // row 0..63 (chunk 1 adds 64)
    const int sc = (tid & 3) * 4;          // word offset 0,4,8,12

    uint4 pva0, pva1, pvb0, pvb1;          // 16 prefetch regs
    auto ldg = [&](int k0w) {
        pva0 = *(const uint4*)(Ag + (size_t)sr * KW + k0w + sc);
        pva1 = *(const uint4*)(Ag + (size_t)(sr + 64) * KW + k0w + sc);
        pvb0 = *(const uint4*)(Bg + (size_t)sr * KW + k0w + sc);
        pvb1 = *(const uint4*)(Bg + (size_t)(sr + 64) * KW + k0w + sc);
    };
    auto sts = [&](int st) {
        *(uint4*)&As[st][sr * 24 + sc]        = pva0;
        *(uint4*)&As[st][(sr + 64) * 24 + sc] = pva1;
        *(uint4*)&Bs[st][sr * 24 + sc]        = pvb0;
        *(uint4*)&Bs[st][(sr + 64) * 24 + sc] = pvb1;
    };

    float acc[4][4][4];
#pragma unroll
    for (int i = 0; i < 4; ++i)
#pragma unroll
        for (int jj = 0; jj < 4; ++jj)
#pragma unroll
            for (int r = 0; r < 4; ++r) acc[i][jj][r] = 0.f;

    ldg(0); sts(0);
    __syncthreads();

    for (int it = 0; it < NIT; ++it) {
        if (it + 1 < NIT) ldg((it + 1) * 16);       // overlaps mma below
        const int cur = it & 1;
        const uint32_t* Ac = As[cur];
        const uint32_t* Bc = Bs[cur];

#pragma unroll
        for (int g = 0; g < 2; ++g) {               // two k16 steps
            uint32_t af[4][4];
            uint2 bf2[4];
#pragma unroll
            for (int mt = 0; mt < 4; ++mt) {
                int r = wm * 64 + mt * 16 + (lane >> 2);
                int base = r * 24 + g * 8 + 2 * j;
                uint2 lo = *(const uint2*)&Ac[base];        // (a0, a2)
                uint2 hi = *(const uint2*)&Ac[base + 192];  // row+8: (a1, a3)
                af[mt][0] = lo.x; af[mt][1] = hi.x;
                af[mt][2] = lo.y; af[mt][3] = hi.y;
            }
#pragma unroll
            for (int nt = 0; nt < 4; ++nt) {
                int n = wn * 32 + nt * 8 + (lane >> 2);
                bf2[nt] = *(const uint2*)&Bc[n * 24 + g * 8 + 2 * j]; // (b0,b1)
            }
#pragma unroll
            for (int mt = 0; mt < 4; ++mt)
#pragma unroll
                for (int nt = 0; nt < 4; ++nt)
                    mma_f16(acc[mt][nt], af[mt], (const uint32_t*)&bf2[nt]);
        }

        if (it + 1 < NIT) sts((it + 1) & 1);
        __syncthreads();
    }

#pragma unroll
    for (int mt = 0; mt < 4; ++mt) {
#pragma unroll
        for (int nt = 0; nt < 4; ++nt) {
            int row = m0 + wm * 64 + mt * 16 + (lane >> 2);
            int col = n0 + wn * 32 + nt * 8 + j * 2;
            float b0 = bias[col], b1 = bias[col + 1];
            float* a = acc[mt][nt];
            if (MODE == 1) {
                float2 v0 = { a[0] + b0, a[1] + b1 };
                float2 v1 = { a[2] + b0, a[3] + b1 };
                *(float2*)&Cout[(size_t)row * EMB + col] = v0;
                *(float2*)&Cout[(size_t)(row + 8) * EMB + col] = v1;
            } else {
                uint32_t w0 = h2pk(a[0] + b0, a[1] + b1);
                uint32_t w1 = h2pk(a[2] + b0, a[3] + b1);
                int which = col >> 10, e = col & 1023, h = e >> 6, d = e & 63;
                uint32_t* dst = (which == 0) ? g_qh : (which == 1) ? g_kh : g_vh;
                int b_ = row >> 11;
                size_t base = (size_t)(b_ * HEADS + h) * SEQ;
                dst[(base + (row & 2047)) * 32 + d / 2] = w0;
                dst[(base + ((row + 8) & 2047)) * 32 + d / 2] = w1;
            }
        }
    }
}

// ---------------------------------------------------------------------------
// FP16 tensor-core flash attention (round-14 PASSING compute, unchanged;
// only the g_atth store position is pair-interleaved for hgemm<1>).
// grid (SEQ/128, BATCH*HEADS), 256 threads = 8 warps x 16 query rows.
// ---------------------------------------------------------------------------
__global__ __launch_bounds__(256)
void fattn_h()
{
    __shared__ uint32_t smem[4608];          // 18 KB
    uint32_t* Ks = smem;                     // 64*36
    uint32_t* Vs = smem + 2304;              // 32*72

    const int tid = threadIdx.x, lane = tid & 31, wid = tid >> 5;
    const int j = lane & 3;
    const int bh = blockIdx.y, q0 = blockIdx.x * 128;

    const uint32_t* Qg = g_qh + ((size_t)bh * SEQ + q0) * 32;   // 32 words/row
    const uint32_t* Kg = g_kh + (size_t)bh * SEQ * 32;
    const uint32_t* Vg = g_vh + (size_t)bh * SEQ * 32;

    // ---- stage Q (128 rows x 32 words), stride 36; lift frags to regs
#pragma unroll
    for (int l = 0; l < 4; ++l) {
        int id = tid + l * 256;              // 0..1023 (uint4 chunks)
        int row = id >> 3, cw = (id & 7) * 4;
        *(uint4*)&smem[row * 36 + cw] = *(const uint4*)(Qg + row * 32 + cw);
    }
    __syncthreads();

    uint32_t qf[4][4];
    {
        int r = wid * 16 + (lane >> 2);
#pragma unroll
        for (int kt = 0; kt < 4; ++kt) {
            int base = r * 36 + kt * 8 + j;
            qf[kt][0] = smem[base];
            qf[kt][1] = smem[base + 8 * 36];
            qf[kt][2] = smem[base + 4];
            qf[kt][3] = smem[base + 8 * 36 + 4];
        }
    }
    __syncthreads();

    float oacc[8][4];
#pragma unroll
    for (int i = 0; i < 8; ++i)
#pragma unroll
        for (int r = 0; r < 4; ++r) oacc[i][r] = 0.f;
    float mrun0 = -1e30f, mrun1 = -1e30f;
    float lrun0 = 0.f, lrun1 = 0.f;
    const float C2 = 0.18033688f;            // log2(e) / sqrt(64)

    for (int t = 0; t < SEQ / 64; ++t) {
        const uint32_t* Kt = Kg + (size_t)t * 64 * 32;
        const uint32_t* Vt = Vg + (size_t)t * 64 * 32;
#pragma unroll
        for (int l = 0; l < 2; ++l) {
            int id = tid + l * 256;
            int n = id >> 3, cw = (id & 7) * 4;
            *(uint4*)&Ks[n * 36 + cw] = *(const uint4*)(Kt + n * 32 + cw);
        }
#pragma unroll
        for (int l = 0; l < 2; ++l) {
            int id = tid + l * 256;
            int kp = id >> 4, d4 = (id & 15) * 4;
            uint2 r0 = *(const uint2*)(Vt + (2 * kp) * 32 + d4 / 2);
            uint2 r1 = *(const uint2*)(Vt + (2 * kp + 1) * 32 + d4 / 2);
            uint4 w = make_uint4(__byte_perm(r0.x, r1.x, 0x5410),
                                 __byte_perm(r0.x, r1.x, 0x7632),
                                 __byte_perm(r0.y, r1.y, 0x5410),
                                 __byte_perm(r0.y, r1.y, 0x7632));
            *(uint4*)&Vs[kp * 72 + d4] = w;
        }
        __syncthreads();

        float sacc[8][4];
#pragma unroll
        for (int i = 0; i < 8; ++i)
#pragma unroll
            for (int r = 0; r < 4; ++r) sacc[i][r] = 0.f;
#pragma unroll
        for (int nt = 0; nt < 8; ++nt) {
            int n = nt * 8 + (lane >> 2);
#pragma unroll
            for (int kt = 0; kt < 4; ++kt) {
                int base = n * 36 + kt * 8 + j;
                uint32_t kf[2] = { Ks[base], Ks[base + 4] };
                mma_f16(sacc[nt], qf[kt], kf);
            }
        }

        float mx0 = -1e30f, mx1 = -1e30f;
#pragma unroll
        for (int i = 0; i < 8; ++i) {
            mx0 = fmaxf(mx0, fmaxf(sacc[i][0], sacc[i][1]));
            mx1 = fmaxf(mx1, fmaxf(sacc[i][2], sacc[i][3]));
        }
        mx0 = fmaxf(mx0, __shfl_xor_sync(0xffffffffu, mx0, 1));
        mx0 = fmaxf(mx0, __shfl_xor_sync(0xffffffffu, mx0, 2));
        mx1 = fmaxf(mx1, __shfl_xor_sync(0xffffffffu, mx1, 1));
        mx1 = fmaxf(mx1, __shfl_xor_sync(0xffffffffu, mx1, 2));
        float mn0 = fmaxf(mrun0, mx0), mn1 = fmaxf(mrun1, mx1);
        float c0 = ex2f((mrun0 - mn0) * C2), c1 = ex2f((mrun1 - mn1) * C2);
        mrun0 = mn0; mrun1 = mn1;
#pragma unroll
        for (int i = 0; i < 8; ++i) {
            oacc[i][0] *= c0; oacc[i][1] *= c0;
            oacc[i][2] *= c1; oacc[i][3] *= c1;
        }
        lrun0 *= c0; lrun1 *= c1;

#pragma unroll
        for (int kt = 0; kt < 4; ++kt) {
            float p00 = ex2f((sacc[2*kt  ][0] - mn0) * C2);
            float p01 = ex2f((sacc[2*kt  ][1] - mn0) * C2);
            float p02 = ex2f((sacc[2*kt  ][2] - mn1) * C2);
            float p03 = ex2f((sacc[2*kt  ][3] - mn1) * C2);
            float p10 = ex2f((sacc[2*kt+1][0] - mn0) * C2);
            float p11 = ex2f((sacc[2*kt+1][1] - mn0) * C2);
            float p12 = ex2f((sacc[2*kt+1][2] - mn1) * C2);
            float p13 = ex2f((sacc[2*kt+1][3] - mn1) * C2);
            lrun0 += p00 + p01 + p10 + p11;
            lrun1 += p02 + p03 + p12 + p13;

            uint32_t pa[4];
            pa[0] = h2pk(p00, p01);
            pa[1] = h2pk(p02, p03);
            pa[2] = h2pk(p10, p11);
            pa[3] = h2pk(p12, p13);

#pragma unroll
            for (int nt = 0; nt < 8; ++nt) {
                int base = (kt * 8 + j) * 72 + nt * 8 + (lane >> 2);
                uint32_t vf[2] = { Vs[base], Vs[base + 4 * 72] };
                mma_f16(oacc[nt], pa, vf);
            }
        }
        __syncthreads();
    }

    // ---- epilogue: quad-reduce l, normalize, store pair-interleaved words
    lrun0 += __shfl_xor_sync(0xffffffffu, lrun0, 1);
    lrun0 += __shfl_xor_sync(0xffffffffu, lrun0, 2);
    lrun1 += __shfl_xor_sync(0xffffffffu, lrun1, 1);
    lrun1 += __shfl_xor_sync(0xffffffffu, lrun1, 2);
    float inv0 = 1.f / lrun0;
    float inv1 = 1.f / lrun1;

    int b_ = bh >> 4, h = bh & 15;
    int row = q0 + wid * 16 + (lane >> 2);
    size_t base0w = (((size_t)b_ * SEQ + row) * EMB + h * HDIM) / 2;
    size_t base1w = base0w + (size_t)4 * EMB;     // +8 rows in words
#pragma unroll
    for (int nt = 0; nt < 8; ++nt) {
        // original word dw = nt*4+j -> interleaved pos within its 8-word group
        int pw = (nt >> 1) * 8 + 2 * j + (nt & 1);
        g_atth[base0w + pw] = h2pk(oacc[nt][0] * inv0, oacc[nt][1] * inv0);
        g_atth[base1w + pw] = h2pk(oacc[nt][2] * inv1, oacc[nt][3] * inv1);
    }
}

// ---------------------------------------------------------------------------
extern "C" void kernel_launch(void* const* d_in, const int* in_sizes, int n_in,
                              void* d_out, int out_size)
{
    const float* x      = (const float*)d_in[0];
    const float* w_qkv  = (const float*)d_in[1];
    const float* b_qkv  = (const float*)d_in[2];
    const float* w_proj = (const float*)d_in[3];
    const float* b_proj = (const float*)d_in[4];
    float* out = (float*)d_out;

    { int n4 = MTOT * EMB / 4;  f2h<0><<<(n4 + 255) / 256, 256>>>((const float4*)x, n4); }
    { int n4 = QKVN * EMB / 4;  f2h<1><<<(n4 + 255) / 256, 256>>>((const float4*)w_qkv, n4); }
    { int n4 = EMB * EMB / 4;   f2h<2><<<(n4 + 255) / 256, 256>>>((const float4*)w_proj, n4); }

    hgemm<0><<<dim3(QKVN / 128, MTOT / 128), 256>>>(b_qkv, nullptr);    // (24,64)

    fattn_h<<<dim3(SEQ / 128, BATCH * HEADS), 256>>>();                 // (16,64)

    hgemm<1><<<dim3(EMB / 128, MTOT / 128), 256>>>(b_proj, out);        // (8,64)
}